// round 2
// baseline (speedup 1.0000x reference)
#include <cuda_runtime.h>
#include <math.h>

// Problem constants
#define DIMN 1024
#define SEQL 2048
#define BATCH 4
#define NHEADS 8
#define HDIM 128
#define NROWS (BATCH*SEQL)   // 8192
#define NPROJ (5*DIMN)       // 5120
#define NBR (2*DIMN)         // 2048

// Scratch (static __device__ arrays -- allocation-free per harness rules)
__device__ float g_h[(size_t)NROWS*DIMN];       // LayerNorm output
__device__ float g_proj[(size_t)NROWS*NPROJ];   // qkv+lin+pre projection
__device__ float g_branch[(size_t)NROWS*NBR];   // [geglu | attn]

typedef unsigned long long u64;

__device__ __forceinline__ u64 pack2(float lo, float hi) {
    u64 r; asm("mov.b64 %0, {%1, %2};" : "=l"(r) : "f"(lo), "f"(hi)); return r;
}
__device__ __forceinline__ void ffma2(u64& d, u64 a, u64 b) {
    asm("fma.rn.f32x2 %0, %1, %2, %0;" : "+l"(d) : "l"(a), "l"(b));
}
__device__ __forceinline__ float2 unpack2(u64 v) {
    float2 f; asm("mov.b64 {%0, %1}, %2;" : "=f"(f.x), "=f"(f.y) : "l"(v)); return f;
}

// ---------------------------------------------------------------------------
// LayerNorm: one block per row of 1024
// ---------------------------------------------------------------------------
__global__ __launch_bounds__(256) void ln_kernel(
    const float* __restrict__ x, const float* __restrict__ gamma,
    const float* __restrict__ beta, float* __restrict__ out)
{
    int row = blockIdx.x, tid = threadIdx.x;
    const float4 v = reinterpret_cast<const float4*>(x + (size_t)row*DIMN)[tid];
    float s  = v.x + v.y + v.z + v.w;
    float sq = v.x*v.x + v.y*v.y + v.z*v.z + v.w*v.w;
    #pragma unroll
    for (int off = 16; off; off >>= 1) {
        s  += __shfl_xor_sync(0xffffffffu, s,  off);
        sq += __shfl_xor_sync(0xffffffffu, sq, off);
    }
    __shared__ float rs[8], rq[8];
    int w = tid >> 5, ln = tid & 31;
    if (ln == 0) { rs[w] = s; rq[w] = sq; }
    __syncthreads();
    s = 0.f; sq = 0.f;
    #pragma unroll
    for (int i = 0; i < 8; i++) { s += rs[i]; sq += rq[i]; }
    float mean = s * (1.f/DIMN);
    float var  = sq * (1.f/DIMN) - mean*mean;
    float rstd = rsqrtf(var + 1e-5f);
    float4 gv = reinterpret_cast<const float4*>(gamma)[tid];
    float4 bv = reinterpret_cast<const float4*>(beta)[tid];
    float4 r;
    r.x = (v.x-mean)*rstd*gv.x + bv.x;
    r.y = (v.y-mean)*rstd*gv.y + bv.y;
    r.z = (v.z-mean)*rstd*gv.z + bv.z;
    r.w = (v.w-mean)*rstd*gv.w + bv.w;
    reinterpret_cast<float4*>(out + (size_t)row*DIMN)[tid] = r;
}

// ---------------------------------------------------------------------------
// SGEMM (NT): C[M,N] = A[M,K] @ B[N,K]^T  (+ optional residual Cin)
// 128x128 block tile, BK=16, 256 threads, 8x8 micro-tile via packed f32x2 FMA.
// A is duplicated into both f32x2 lanes in smem; B pairs naturally along N.
// ---------------------------------------------------------------------------
template<bool ADD>
__global__ __launch_bounds__(256, 1) void sgemm_nt(
    const float* __restrict__ A, const float* __restrict__ Bm,
    const float* __restrict__ Cin, float* __restrict__ C,
    int M, int N, int K)
{
    __shared__ u64   As2[16*128];   // [k][m], lanes duplicated
    __shared__ float Bs [16*128];   // [k][n]
    const int tid = threadIdx.x;
    const int tx = tid & 15, ty = tid >> 4;
    const int rowBase = blockIdx.y * 128;
    const int colBase = blockIdx.x * 128;

    u64 acc[8][4];
    #pragma unroll
    for (int i = 0; i < 8; i++)
        #pragma unroll
        for (int j = 0; j < 4; j++) acc[i][j] = 0ull;

    auto gload = [&](int kt, float4* ga, float4* gb) {
        #pragma unroll
        for (int i = 0; i < 2; i++) {
            int idx4 = tid + i*256;
            int r = idx4 >> 2, c4 = idx4 & 3;
            ga[i] = *reinterpret_cast<const float4*>(&A [(size_t)(rowBase + r)*K + kt + c4*4]);
            gb[i] = *reinterpret_cast<const float4*>(&Bm[(size_t)(colBase + r)*K + kt + c4*4]);
        }
    };
    auto sstore = [&](const float4* ga, const float4* gb) {
        #pragma unroll
        for (int i = 0; i < 2; i++) {
            int idx4 = tid + i*256;
            int r = idx4 >> 2, c4 = idx4 & 3;
            As2[(c4*4+0)*128 + r] = pack2(ga[i].x, ga[i].x);
            As2[(c4*4+1)*128 + r] = pack2(ga[i].y, ga[i].y);
            As2[(c4*4+2)*128 + r] = pack2(ga[i].z, ga[i].z);
            As2[(c4*4+3)*128 + r] = pack2(ga[i].w, ga[i].w);
            Bs [(c4*4+0)*128 + r] = gb[i].x;
            Bs [(c4*4+1)*128 + r] = gb[i].y;
            Bs [(c4*4+2)*128 + r] = gb[i].z;
            Bs [(c4*4+3)*128 + r] = gb[i].w;
        }
    };

    float4 ga[2], gb[2];
    gload(0, ga, gb);
    sstore(ga, gb);
    __syncthreads();

    for (int kt = 16; ; kt += 16) {
        const bool more = (kt < K);
        float4 nga[2], ngb[2];
        if (more) gload(kt, nga, ngb);      // prefetch next tile while computing
        #pragma unroll
        for (int k = 0; k < 16; k++) {
            u64 a[8];
            #pragma unroll
            for (int i = 0; i < 8; i++) a[i] = As2[k*128 + ty*8 + i];
            u64 b[4];
            const u64* bp = reinterpret_cast<const u64*>(&Bs[k*128 + tx*8]);
            #pragma unroll
            for (int j = 0; j < 4; j++) b[j] = bp[j];
            #pragma unroll
            for (int i = 0; i < 8; i++)
                #pragma unroll
                for (int j = 0; j < 4; j++) ffma2(acc[i][j], a[i], b[j]);
        }
        if (!more) break;
        __syncthreads();
        sstore(nga, ngb);
        __syncthreads();
    }

    #pragma unroll
    for (int i = 0; i < 8; i++) {
        int row = rowBase + ty*8 + i;
        #pragma unroll
        for (int j = 0; j < 4; j++) {
            float2 f = unpack2(acc[i][j]);
            size_t o = (size_t)row*N + colBase + tx*8 + j*2;
            if (ADD) { f.x += Cin[o]; f.y += Cin[o+1]; }
            C[o]   = f.x;
            C[o+1] = f.y;
        }
    }
}

// ---------------------------------------------------------------------------
// GEGLU branch: branch[:, 0:1024] = lin * gelu_exact(pre)
// ---------------------------------------------------------------------------
__device__ __forceinline__ float gelu_exact(float v) {
    return 0.5f * v * (1.f + erff(v * 0.70710678118654752440f));
}
__global__ __launch_bounds__(256) void glu_kernel(
    const float* __restrict__ proj, float* __restrict__ branch)
{
    int idx = blockIdx.x * 256 + threadIdx.x;   // float4 index
    int r  = idx >> 8;           // 256 float4s per 1024-col row
    int c4 = idx & 255;
    float4 lin = *reinterpret_cast<const float4*>(&proj[(size_t)r*NPROJ + 3*DIMN + c4*4]);
    float4 pre = *reinterpret_cast<const float4*>(&proj[(size_t)r*NPROJ + 4*DIMN + c4*4]);
    float4 o;
    o.x = lin.x * gelu_exact(pre.x);
    o.y = lin.y * gelu_exact(pre.y);
    o.z = lin.z * gelu_exact(pre.z);
    o.w = lin.w * gelu_exact(pre.w);
    *reinterpret_cast<float4*>(&branch[(size_t)r*NBR + c4*4]) = o;
}

// ---------------------------------------------------------------------------
// Causal flash attention with power-softmax p=2.
//   probs = exp(s - lse),  lse = m + 0.5*log(sum exp(2(s-m)))
//   out   = [sum exp(s-m) v] / sqrt(sum exp(2(s-m)))
// BQ=BK=64, hd=128, 256 threads (16x16). Phase1: 4x4 score micro-tile.
// Phase2: each thread owns O[4 rows][8 cols]. Skips all future (masked) tiles.
// Writes result into branch[:, 1024:2048].
// ---------------------------------------------------------------------------
__global__ __launch_bounds__(256, 1) void attn_kernel(
    const float* __restrict__ proj, float* __restrict__ branch)
{
    extern __shared__ float sm[];
    float* Qst = sm;                 // [128][64]  (d-major, transposed)
    float* Kst = Qst + 128*64;       // [128][64]
    float* Vs  = Kst + 128*64;       // [64][128]
    float* Ps  = Vs  + 64*128;       // [64][65]

    const int tid = threadIdx.x;
    const int tx = tid & 15, ty = tid >> 4;
    const int qb = blockIdx.x;                 // query tile (0..31)
    const int bh = blockIdx.y;
    const int b = bh >> 3, h = bh & 7;
    const float scale = 0.08838834764831845f;  // 1/sqrt(128)

    const size_t rowOff = (size_t)(b * SEQL) * NPROJ;
    const int colQ = h*HDIM, colK = DIMN + h*HDIM, colV = 2*DIMN + h*HDIM;

    // Load Q tile (transposed into Qst[d][r])
    #pragma unroll
    for (int i = 0; i < 8; i++) {
        int idx4 = tid + i*256;
        int r = idx4 >> 5, d4 = idx4 & 31;
        float4 v = *reinterpret_cast<const float4*>(
            &proj[rowOff + (size_t)(qb*64 + r)*NPROJ + colQ + d4*4]);
        Qst[(d4*4+0)*64 + r] = v.x;
        Qst[(d4*4+1)*64 + r] = v.y;
        Qst[(d4*4+2)*64 + r] = v.z;
        Qst[(d4*4+3)*64 + r] = v.w;
    }

    float O[4][8];
    float m[4], S2[4];
    #pragma unroll
    for (int i = 0; i < 4; i++) {
        m[i] = -INFINITY; S2[i] = 0.f;
        #pragma unroll
        for (int j = 0; j < 8; j++) O[i][j] = 0.f;
    }

    for (int kb = 0; kb <= qb; kb++) {
        __syncthreads();   // previous phase2 done reading Vs; also covers Q load at kb=0
        // Load K (transposed) and V tiles
        #pragma unroll
        for (int i = 0; i < 8; i++) {
            int idx4 = tid + i*256;
            int r = idx4 >> 5, d4 = idx4 & 31;
            float4 kv = *reinterpret_cast<const float4*>(
                &proj[rowOff + (size_t)(kb*64 + r)*NPROJ + colK + d4*4]);
            Kst[(d4*4+0)*64 + r] = kv.x;
            Kst[(d4*4+1)*64 + r] = kv.y;
            Kst[(d4*4+2)*64 + r] = kv.z;
            Kst[(d4*4+3)*64 + r] = kv.w;
            float4 vv = *reinterpret_cast<const float4*>(
                &proj[rowOff + (size_t)(kb*64 + r)*NPROJ + colV + d4*4]);
            *reinterpret_cast<float4*>(&Vs[r*128 + d4*4]) = vv;
        }
        __syncthreads();

        // Phase 1: scores S[4][4] = Q Kt over d
        float s[4][4];
        #pragma unroll
        for (int i = 0; i < 4; i++)
            #pragma unroll
            for (int j = 0; j < 4; j++) s[i][j] = 0.f;
        #pragma unroll 4
        for (int d = 0; d < 128; d++) {
            float4 qv = *reinterpret_cast<const float4*>(&Qst[d*64 + ty*4]);
            float4 kv = *reinterpret_cast<const float4*>(&Kst[d*64 + tx*4]);
            float qa[4] = {qv.x, qv.y, qv.z, qv.w};
            float ka[4] = {kv.x, kv.y, kv.z, kv.w};
            #pragma unroll
            for (int i = 0; i < 4; i++)
                #pragma unroll
                for (int j = 0; j < 4; j++) s[i][j] += qa[i]*ka[j];
        }

        // online p=2 softmax update
        const bool diag = (kb == qb);
        #pragma unroll
        for (int i = 0; i < 4; i++) {
            int qg = qb*64 + ty*4 + i;
            float tm = -INFINITY;
            #pragma unroll
            for (int j = 0; j < 4; j++) {
                int kg = kb*64 + tx*4 + j;
                float v = s[i][j] * scale;
                if (diag && kg > qg) v = -INFINITY;
                s[i][j] = v;
                tm = fmaxf(tm, v);
            }
            #pragma unroll
            for (int off = 1; off < 16; off <<= 1)
                tm = fmaxf(tm, __shfl_xor_sync(0xffffffffu, tm, off));
            float mn = fmaxf(m[i], tm);
            float corr = expf(m[i] - mn);   // 0 when m was -inf
            m[i] = mn;
            float rs2 = 0.f;
            #pragma unroll
            for (int j = 0; j < 4; j++) {
                float p = expf(s[i][j] - mn);   // masked -> 0
                s[i][j] = p;
                rs2 += p*p;
            }
            #pragma unroll
            for (int off = 1; off < 16; off <<= 1)
                rs2 += __shfl_xor_sync(0xffffffffu, rs2, off);
            S2[i] = S2[i]*corr*corr + rs2;
            #pragma unroll
            for (int j = 0; j < 8; j++) O[i][j] *= corr;
            #pragma unroll
            for (int j = 0; j < 4; j++)
                Ps[(ty*4+i)*65 + tx*4 + j] = s[i][j];
        }
        __syncthreads();

        // Phase 2: O += P @ V
        #pragma unroll 2
        for (int kc = 0; kc < 64; kc++) {
            float4 v0 = *reinterpret_cast<const float4*>(&Vs[kc*128 + tx*8]);
            float4 v1 = *reinterpret_cast<const float4*>(&Vs[kc*128 + tx*8 + 4]);
            float vv[8] = {v0.x, v0.y, v0.z, v0.w, v1.x, v1.y, v1.z, v1.w};
            #pragma unroll
            for (int i = 0; i < 4; i++) {
                float p = Ps[(ty*4+i)*65 + kc];
                #pragma unroll
                for (int j = 0; j < 8; j++) O[i][j] += p * vv[j];
            }
        }
    }

    // Final scale and store into branch[:, 1024 + h*128 + ...]
    #pragma unroll
    for (int i = 0; i < 4; i++) {
        float inv = rsqrtf(S2[i]);
        int rg = b*SEQL + qb*64 + ty*4 + i;
        float4 o0 = make_float4(O[i][0]*inv, O[i][1]*inv, O[i][2]*inv, O[i][3]*inv);
        float4 o1 = make_float4(O[i][4]*inv, O[i][5]*inv, O[i][6]*inv, O[i][7]*inv);
        size_t base = (size_t)rg*NBR + DIMN + h*HDIM + tx*8;
        *reinterpret_cast<float4*>(&branch[base])     = o0;
        *reinterpret_cast<float4*>(&branch[base + 4]) = o1;
    }
}

// ---------------------------------------------------------------------------
// Launch
// ---------------------------------------------------------------------------
extern "C" void kernel_launch(void* const* d_in, const int* in_sizes, int n_in,
                              void* d_out, int out_size)
{
    const float* x     = (const float*)d_in[0];
    const float* gamma = (const float*)d_in[1];
    const float* beta  = (const float*)d_in[2];
    const float* w_qkv = (const float*)d_in[3];
    const float* w_out = (const float*)d_in[4];
    float* out = (float*)d_out;

    float *hbuf, *projbuf, *branchbuf;
    cudaGetSymbolAddress((void**)&hbuf,      g_h);
    cudaGetSymbolAddress((void**)&projbuf,   g_proj);
    cudaGetSymbolAddress((void**)&branchbuf, g_branch);

    const int attn_smem = (128*64 + 128*64 + 64*128 + 64*65) * (int)sizeof(float);
    cudaFuncSetAttribute(attn_kernel, cudaFuncAttributeMaxDynamicSharedMemorySize, attn_smem);

    // 1) LayerNorm
    ln_kernel<<<NROWS, 256>>>(x, gamma, beta, hbuf);

    // 2) proj = h @ w_qkv^T   [8192 x 5120], K=1024
    {
        dim3 grid(NPROJ/128, NROWS/128);
        sgemm_nt<false><<<grid, 256>>>(hbuf, w_qkv, nullptr, projbuf, NROWS, NPROJ, DIMN);
    }

    // 3) GEGLU half of branch
    glu_kernel<<<(NROWS*DIMN)/4/256, 256>>>(projbuf, branchbuf);

    // 4) Attention half of branch
    {
        dim3 grid(SEQL/64, BATCH*NHEADS);
        attn_kernel<<<grid, 256, attn_smem>>>(projbuf, branchbuf);
    }

    // 5) out = x + branch @ w_out^T   [8192 x 1024], K=2048
    {
        dim3 grid(DIMN/128, NROWS/128);
        sgemm_nt<true><<<grid, 256>>>(branchbuf, w_out, x, out, NROWS, DIMN, NBR);
    }
}

// round 5
// speedup vs baseline: 1.2513x; 1.2513x over previous
#include <cuda_runtime.h>
#include <math.h>
#include <stdint.h>

// Problem constants
#define DIMN 1024
#define SEQL 2048
#define BATCH 4
#define NHEADS 8
#define HDIM 128
#define NROWS (BATCH*SEQL)   // 8192
#define NPROJ (5*DIMN)       // 5120
#define NBR (2*DIMN)         // 2048

// Scratch (static __device__ arrays -- allocation-free per harness rules)
__device__ float g_h[(size_t)NROWS*DIMN];       // LayerNorm output
__device__ float g_proj[(size_t)NROWS*NPROJ];   // qkv+lin+pre projection
__device__ float g_branch[(size_t)NROWS*NBR];   // [geglu | attn]

// ===========================================================================
// mma.sync tf32 helpers (non-'a' PTX features only -- tcgen05 rejected by the
// harness's compute_103 virtual arch)
// ===========================================================================
__device__ __forceinline__ uint32_t f2tf(float x) {
    uint32_t r; asm("cvt.rna.tf32.f32 %0, %1;" : "=r"(r) : "f"(x)); return r;
}
__device__ __forceinline__ void mma_tf32(float* c, const uint32_t* a,
                                         const uint32_t* b) {
    asm volatile(
        "mma.sync.aligned.m16n8k8.row.col.f32.tf32.tf32.f32 "
        "{%0,%1,%2,%3}, {%4,%5,%6,%7}, {%8,%9}, {%0,%1,%2,%3};"
        : "+f"(c[0]), "+f"(c[1]), "+f"(c[2]), "+f"(c[3])
        : "r"(a[0]), "r"(a[1]), "r"(a[2]), "r"(a[3]), "r"(b[0]), "r"(b[1]));
}

// ---------------------------------------------------------------------------
// LayerNorm: one block per row of 1024
// ---------------------------------------------------------------------------
__global__ __launch_bounds__(256) void ln_kernel(
    const float* __restrict__ x, const float* __restrict__ gamma,
    const float* __restrict__ beta, float* __restrict__ out)
{
    int row = blockIdx.x, tid = threadIdx.x;
    const float4 v = reinterpret_cast<const float4*>(x + (size_t)row*DIMN)[tid];
    float s  = v.x + v.y + v.z + v.w;
    float sq = v.x*v.x + v.y*v.y + v.z*v.z + v.w*v.w;
    #pragma unroll
    for (int off = 16; off; off >>= 1) {
        s  += __shfl_xor_sync(0xffffffffu, s,  off);
        sq += __shfl_xor_sync(0xffffffffu, sq, off);
    }
    __shared__ float rs[8], rq[8];
    int w = tid >> 5, ln = tid & 31;
    if (ln == 0) { rs[w] = s; rq[w] = sq; }
    __syncthreads();
    s = 0.f; sq = 0.f;
    #pragma unroll
    for (int i = 0; i < 8; i++) { s += rs[i]; sq += rq[i]; }
    float mean = s * (1.f/DIMN);
    float var  = sq * (1.f/DIMN) - mean*mean;
    float rstd = rsqrtf(var + 1e-5f);
    float4 gv = reinterpret_cast<const float4*>(gamma)[tid];
    float4 bv = reinterpret_cast<const float4*>(beta)[tid];
    float4 r;
    r.x = (v.x-mean)*rstd*gv.x + bv.x;
    r.y = (v.y-mean)*rstd*gv.y + bv.y;
    r.z = (v.z-mean)*rstd*gv.z + bv.z;
    r.w = (v.w-mean)*rstd*gv.w + bv.w;
    reinterpret_cast<float4*>(out + (size_t)row*DIMN)[tid] = r;
}

// ---------------------------------------------------------------------------
// 3xTF32 mma.sync GEMM (NT): C[M,N] = A[M,K] @ B[N,K]^T (+ optional Cin)
// CTA 128x128, BK=32, 8 warps (2x4) of 64x32 warp tiles.
// fp32 split hi/lo at STS time into 4 smem tiles [128][36] (pad -> bank-clean).
// 3 mma per (mt,nt,k8): Ah*Bh + Ah*Bl + Al*Bh.
// ---------------------------------------------------------------------------
#define SPAD 36
#define MM_SMEM (4*128*SPAD*4)     // 73728 B

template<bool ADD>
__global__ __launch_bounds__(256, 2)
void mm_mma(const float* __restrict__ A, const float* __restrict__ Bm,
            const float* __restrict__ Cin, float* __restrict__ C,
            int M, int N, int K)
{
    extern __shared__ uint32_t sm4[];
    uint32_t* Ah = sm4;
    uint32_t* Al = Ah + 128*SPAD;
    uint32_t* Bh = Al + 128*SPAD;
    uint32_t* Bl = Bh + 128*SPAD;

    const int tid  = threadIdx.x;
    const int warp = tid >> 5, lane = tid & 31;
    const int g = lane >> 2, t4 = lane & 3;
    const int wm = (warp >> 2) * 64;     // warp row base (0 or 64)
    const int wn = (warp & 3) * 32;      // warp col base (0..96)
    const int rowBase = blockIdx.y * 128;
    const int colBase = blockIdx.x * 128;

    float acc[4][4][4];
    #pragma unroll
    for (int i = 0; i < 4; i++)
        #pragma unroll
        for (int j = 0; j < 4; j++)
            #pragma unroll
            for (int q = 0; q < 4; q++) acc[i][j][q] = 0.f;

    const int NKB = K >> 5;
    for (int kb = 0; kb < NKB; kb++) {
        __syncthreads();   // previous compute finished reading smem
        // Load + split + store: 512 chunks of float8 per matrix.
        #pragma unroll
        for (int i = 0; i < 2; i++) {
            int c = i*256 + tid;
            int r = c & 127, q = c >> 7;     // row, k8-group
            // ---- A ----
            {
                const float* src = A + (size_t)(rowBase + r)*K + kb*32 + q*8;
                float4 v0 = *reinterpret_cast<const float4*>(src);
                float4 v1 = *reinterpret_cast<const float4*>(src + 4);
                uint4 h0, h1, l0, l1;
                h0.x = f2tf(v0.x); l0.x = f2tf(v0.x - __uint_as_float(h0.x));
                h0.y = f2tf(v0.y); l0.y = f2tf(v0.y - __uint_as_float(h0.y));
                h0.z = f2tf(v0.z); l0.z = f2tf(v0.z - __uint_as_float(h0.z));
                h0.w = f2tf(v0.w); l0.w = f2tf(v0.w - __uint_as_float(h0.w));
                h1.x = f2tf(v1.x); l1.x = f2tf(v1.x - __uint_as_float(h1.x));
                h1.y = f2tf(v1.y); l1.y = f2tf(v1.y - __uint_as_float(h1.y));
                h1.z = f2tf(v1.z); l1.z = f2tf(v1.z - __uint_as_float(h1.z));
                h1.w = f2tf(v1.w); l1.w = f2tf(v1.w - __uint_as_float(h1.w));
                int o = r*SPAD + q*8;
                *reinterpret_cast<uint4*>(Ah + o)     = h0;
                *reinterpret_cast<uint4*>(Ah + o + 4) = h1;
                *reinterpret_cast<uint4*>(Al + o)     = l0;
                *reinterpret_cast<uint4*>(Al + o + 4) = l1;
            }
            // ---- B ----
            {
                const float* src = Bm + (size_t)(colBase + r)*K + kb*32 + q*8;
                float4 v0 = *reinterpret_cast<const float4*>(src);
                float4 v1 = *reinterpret_cast<const float4*>(src + 4);
                uint4 h0, h1, l0, l1;
                h0.x = f2tf(v0.x); l0.x = f2tf(v0.x - __uint_as_float(h0.x));
                h0.y = f2tf(v0.y); l0.y = f2tf(v0.y - __uint_as_float(h0.y));
                h0.z = f2tf(v0.z); l0.z = f2tf(v0.z - __uint_as_float(h0.z));
                h0.w = f2tf(v0.w); l0.w = f2tf(v0.w - __uint_as_float(h0.w));
                h1.x = f2tf(v1.x); l1.x = f2tf(v1.x - __uint_as_float(h1.x));
                h1.y = f2tf(v1.y); l1.y = f2tf(v1.y - __uint_as_float(h1.y));
                h1.z = f2tf(v1.z); l1.z = f2tf(v1.z - __uint_as_float(h1.z));
                h1.w = f2tf(v1.w); l1.w = f2tf(v1.w - __uint_as_float(h1.w));
                int o = r*SPAD + q*8;
                *reinterpret_cast<uint4*>(Bh + o)     = h0;
                *reinterpret_cast<uint4*>(Bh + o + 4) = h1;
                *reinterpret_cast<uint4*>(Bl + o)     = l0;
                *reinterpret_cast<uint4*>(Bl + o + 4) = l1;
            }
        }
        __syncthreads();

        // Compute: 4 k8 steps
        #pragma unroll
        for (int kk = 0; kk < 4; kk++) {
            const int k0 = kk*8 + t4;
            uint32_t bh[4][2], bl[4][2];
            #pragma unroll
            for (int nt = 0; nt < 4; nt++) {
                int nrow = wn + nt*8 + g;
                bh[nt][0] = Bh[nrow*SPAD + k0];
                bh[nt][1] = Bh[nrow*SPAD + k0 + 4];
                bl[nt][0] = Bl[nrow*SPAD + k0];
                bl[nt][1] = Bl[nrow*SPAD + k0 + 4];
            }
            #pragma unroll
            for (int mt = 0; mt < 4; mt++) {
                int r0 = (wm + mt*16 + g)*SPAD;
                int r8 = (wm + mt*16 + 8 + g)*SPAD;
                uint32_t ah[4], al[4];
                ah[0] = Ah[r0 + k0];  ah[1] = Ah[r8 + k0];
                ah[2] = Ah[r0 + k0 + 4];  ah[3] = Ah[r8 + k0 + 4];
                al[0] = Al[r0 + k0];  al[1] = Al[r8 + k0];
                al[2] = Al[r0 + k0 + 4];  al[3] = Al[r8 + k0 + 4];
                #pragma unroll
                for (int nt = 0; nt < 4; nt++) {
                    mma_tf32(acc[mt][nt], ah, bh[nt]);
                    mma_tf32(acc[mt][nt], ah, bl[nt]);
                    mma_tf32(acc[mt][nt], al, bh[nt]);
                }
            }
        }
    }

    // Epilogue
    #pragma unroll
    for (int mt = 0; mt < 4; mt++) {
        int row0 = rowBase + wm + mt*16 + g;
        #pragma unroll
        for (int nt = 0; nt < 4; nt++) {
            int col = colBase + wn + nt*8 + t4*2;
            size_t o0 = (size_t)row0*N + col;
            size_t o1 = (size_t)(row0 + 8)*N + col;
            float2 v0 = make_float2(acc[mt][nt][0], acc[mt][nt][1]);
            float2 v1 = make_float2(acc[mt][nt][2], acc[mt][nt][3]);
            if (ADD) {
                float2 c0 = *reinterpret_cast<const float2*>(Cin + o0);
                float2 c1 = *reinterpret_cast<const float2*>(Cin + o1);
                v0.x += c0.x; v0.y += c0.y;
                v1.x += c1.x; v1.y += c1.y;
            }
            *reinterpret_cast<float2*>(C + o0) = v0;
            *reinterpret_cast<float2*>(C + o1) = v1;
        }
    }
}

// ---------------------------------------------------------------------------
// GEGLU branch: branch[:, 0:1024] = lin * gelu_exact(pre)
// ---------------------------------------------------------------------------
__device__ __forceinline__ float gelu_exact(float v) {
    return 0.5f * v * (1.f + erff(v * 0.70710678118654752440f));
}
__global__ __launch_bounds__(256) void glu_kernel(
    const float* __restrict__ proj, float* __restrict__ branch)
{
    int idx = blockIdx.x * 256 + threadIdx.x;   // float4 index
    int r  = idx >> 8;
    int c4 = idx & 255;
    float4 lin = *reinterpret_cast<const float4*>(&proj[(size_t)r*NPROJ + 3*DIMN + c4*4]);
    float4 pre = *reinterpret_cast<const float4*>(&proj[(size_t)r*NPROJ + 4*DIMN + c4*4]);
    float4 o;
    o.x = lin.x * gelu_exact(pre.x);
    o.y = lin.y * gelu_exact(pre.y);
    o.z = lin.z * gelu_exact(pre.z);
    o.w = lin.w * gelu_exact(pre.w);
    *reinterpret_cast<float4*>(&branch[(size_t)r*NBR + c4*4]) = o;
}

// ---------------------------------------------------------------------------
// Causal flash attention with power-softmax p=2 (R2-proven, unchanged).
// ---------------------------------------------------------------------------
__global__ __launch_bounds__(256, 1) void attn_kernel(
    const float* __restrict__ proj, float* __restrict__ branch)
{
    extern __shared__ float sm[];
    float* Qst = sm;                 // [128][64]
    float* Kst = Qst + 128*64;       // [128][64]
    float* Vs  = Kst + 128*64;       // [64][128]
    float* Ps  = Vs  + 64*128;       // [64][65]

    const int tid = threadIdx.x;
    const int tx = tid & 15, ty = tid >> 4;
    const int qb = blockIdx.x;
    const int bh = blockIdx.y;
    const int b = bh >> 3, h = bh & 7;
    const float scale = 0.08838834764831845f;

    const size_t rowOff = (size_t)(b * SEQL) * NPROJ;
    const int colQ = h*HDIM, colK = DIMN + h*HDIM, colV = 2*DIMN + h*HDIM;

    #pragma unroll
    for (int i = 0; i < 8; i++) {
        int idx4 = tid + i*256;
        int r = idx4 >> 5, d4 = idx4 & 31;
        float4 v = *reinterpret_cast<const float4*>(
            &proj[rowOff + (size_t)(qb*64 + r)*NPROJ + colQ + d4*4]);
        Qst[(d4*4+0)*64 + r] = v.x;
        Qst[(d4*4+1)*64 + r] = v.y;
        Qst[(d4*4+2)*64 + r] = v.z;
        Qst[(d4*4+3)*64 + r] = v.w;
    }

    float O[4][8];
    float m[4], S2[4];
    #pragma unroll
    for (int i = 0; i < 4; i++) {
        m[i] = -INFINITY; S2[i] = 0.f;
        #pragma unroll
        for (int j = 0; j < 8; j++) O[i][j] = 0.f;
    }

    for (int kb = 0; kb <= qb; kb++) {
        __syncthreads();
        #pragma unroll
        for (int i = 0; i < 8; i++) {
            int idx4 = tid + i*256;
            int r = idx4 >> 5, d4 = idx4 & 31;
            float4 kv = *reinterpret_cast<const float4*>(
                &proj[rowOff + (size_t)(kb*64 + r)*NPROJ + colK + d4*4]);
            Kst[(d4*4+0)*64 + r] = kv.x;
            Kst[(d4*4+1)*64 + r] = kv.y;
            Kst[(d4*4+2)*64 + r] = kv.z;
            Kst[(d4*4+3)*64 + r] = kv.w;
            float4 vv = *reinterpret_cast<const float4*>(
                &proj[rowOff + (size_t)(kb*64 + r)*NPROJ + colV + d4*4]);
            *reinterpret_cast<float4*>(&Vs[r*128 + d4*4]) = vv;
        }
        __syncthreads();

        float s[4][4];
        #pragma unroll
        for (int i = 0; i < 4; i++)
            #pragma unroll
            for (int j = 0; j < 4; j++) s[i][j] = 0.f;
        #pragma unroll 4
        for (int d = 0; d < 128; d++) {
            float4 qv = *reinterpret_cast<const float4*>(&Qst[d*64 + ty*4]);
            float4 kv = *reinterpret_cast<const float4*>(&Kst[d*64 + tx*4]);
            float qa[4] = {qv.x, qv.y, qv.z, qv.w};
            float ka[4] = {kv.x, kv.y, kv.z, kv.w};
            #pragma unroll
            for (int i = 0; i < 4; i++)
                #pragma unroll
                for (int j = 0; j < 4; j++) s[i][j] += qa[i]*ka[j];
        }

        const bool diag = (kb == qb);
        #pragma unroll
        for (int i = 0; i < 4; i++) {
            int qg = qb*64 + ty*4 + i;
            float tm = -INFINITY;
            #pragma unroll
            for (int j = 0; j < 4; j++) {
                int kg = kb*64 + tx*4 + j;
                float v = s[i][j] * scale;
                if (diag && kg > qg) v = -INFINITY;
                s[i][j] = v;
                tm = fmaxf(tm, v);
            }
            #pragma unroll
            for (int off = 1; off < 16; off <<= 1)
                tm = fmaxf(tm, __shfl_xor_sync(0xffffffffu, tm, off));
            float mn = fmaxf(m[i], tm);
            float corr = expf(m[i] - mn);
            m[i] = mn;
            float rs2 = 0.f;
            #pragma unroll
            for (int j = 0; j < 4; j++) {
                float p = expf(s[i][j] - mn);
                s[i][j] = p;
                rs2 += p*p;
            }
            #pragma unroll
            for (int off = 1; off < 16; off <<= 1)
                rs2 += __shfl_xor_sync(0xffffffffu, rs2, off);
            S2[i] = S2[i]*corr*corr + rs2;
            #pragma unroll
            for (int j = 0; j < 8; j++) O[i][j] *= corr;
            #pragma unroll
            for (int j = 0; j < 4; j++)
                Ps[(ty*4+i)*65 + tx*4 + j] = s[i][j];
        }
        __syncthreads();

        #pragma unroll 2
        for (int kc = 0; kc < 64; kc++) {
            float4 v0 = *reinterpret_cast<const float4*>(&Vs[kc*128 + tx*8]);
            float4 v1 = *reinterpret_cast<const float4*>(&Vs[kc*128 + tx*8 + 4]);
            float vv[8] = {v0.x, v0.y, v0.z, v0.w, v1.x, v1.y, v1.z, v1.w};
            #pragma unroll
            for (int i = 0; i < 4; i++) {
                float p = Ps[(ty*4+i)*65 + kc];
                #pragma unroll
                for (int j = 0; j < 8; j++) O[i][j] += p * vv[j];
            }
        }
    }

    #pragma unroll
    for (int i = 0; i < 4; i++) {
        float inv = rsqrtf(S2[i]);
        int rg = b*SEQL + qb*64 + ty*4 + i;
        float4 o0 = make_float4(O[i][0]*inv, O[i][1]*inv, O[i][2]*inv, O[i][3]*inv);
        float4 o1 = make_float4(O[i][4]*inv, O[i][5]*inv, O[i][6]*inv, O[i][7]*inv);
        size_t base = (size_t)rg*NBR + DIMN + h*HDIM + tx*8;
        *reinterpret_cast<float4*>(&branch[base])     = o0;
        *reinterpret_cast<float4*>(&branch[base + 4]) = o1;
    }
}

// ---------------------------------------------------------------------------
// Launch
// ---------------------------------------------------------------------------
extern "C" void kernel_launch(void* const* d_in, const int* in_sizes, int n_in,
                              void* d_out, int out_size)
{
    const float* x     = (const float*)d_in[0];
    const float* gamma = (const float*)d_in[1];
    const float* beta  = (const float*)d_in[2];
    const float* w_qkv = (const float*)d_in[3];
    const float* w_out = (const float*)d_in[4];
    float* out = (float*)d_out;

    float *hbuf, *projbuf, *branchbuf;
    cudaGetSymbolAddress((void**)&hbuf,      g_h);
    cudaGetSymbolAddress((void**)&projbuf,   g_proj);
    cudaGetSymbolAddress((void**)&branchbuf, g_branch);

    const int attn_smem = (128*64 + 128*64 + 64*128 + 64*65) * (int)sizeof(float);
    cudaFuncSetAttribute(attn_kernel, cudaFuncAttributeMaxDynamicSharedMemorySize, attn_smem);
    cudaFuncSetAttribute(mm_mma<false>, cudaFuncAttributeMaxDynamicSharedMemorySize, MM_SMEM);
    cudaFuncSetAttribute(mm_mma<true>,  cudaFuncAttributeMaxDynamicSharedMemorySize, MM_SMEM);

    // 1) LayerNorm
    ln_kernel<<<NROWS, 256>>>(x, gamma, beta, hbuf);

    // 2) proj = h @ w_qkv^T   [8192 x 5120], K=1024  (3xTF32 mma.sync)
    {
        dim3 grid(NPROJ/128, NROWS/128);
        mm_mma<false><<<grid, 256, MM_SMEM>>>(hbuf, w_qkv, nullptr, projbuf,
                                              NROWS, NPROJ, DIMN);
    }

    // 3) GEGLU half of branch
    glu_kernel<<<(NROWS*DIMN)/4/256, 256>>>(projbuf, branchbuf);

    // 4) Attention half of branch
    {
        dim3 grid(SEQL/64, BATCH*NHEADS);
        attn_kernel<<<grid, 256, attn_smem>>>(projbuf, branchbuf);
    }

    // 5) out = x + branch @ w_out^T   [8192 x 1024], K=2048  (3xTF32 mma.sync)
    {
        dim3 grid(DIMN/128, NROWS/128);
        mm_mma<true><<<grid, 256, MM_SMEM>>>(branchbuf, w_out, x, out,
                                             NROWS, DIMN, NBR);
    }
}

// round 7
// speedup vs baseline: 1.6544x; 1.3221x over previous
#include <cuda_runtime.h>
#include <math.h>
#include <stdint.h>

// Problem constants
#define DIMN 1024
#define SEQL 2048
#define BATCH 4
#define NHEADS 8
#define HDIM 128
#define NROWS (BATCH*SEQL)   // 8192
#define NPROJ (5*DIMN)       // 5120
#define NBR (2*DIMN)         // 2048

// Scratch (static __device__ arrays -- allocation-free per harness rules)
__device__ float g_h[(size_t)NROWS*DIMN];       // LayerNorm output
__device__ float g_proj[(size_t)NROWS*NPROJ];   // qkv+lin+pre projection
__device__ float g_branch[(size_t)NROWS*NBR];   // [geglu | attn]

// ===========================================================================
// mma.sync tf32 helpers (non-'a' PTX features only)
// ===========================================================================
__device__ __forceinline__ uint32_t f2tf(float x) {
    uint32_t r; asm("cvt.rna.tf32.f32 %0, %1;" : "=r"(r) : "f"(x)); return r;
}
__device__ __forceinline__ void split2(float x, uint32_t& h, uint32_t& l) {
    h = f2tf(x);
    l = f2tf(x - __uint_as_float(h));
}
__device__ __forceinline__ void mma_tf32(float* c, const uint32_t* a,
                                         const uint32_t* b) {
    asm volatile(
        "mma.sync.aligned.m16n8k8.row.col.f32.tf32.tf32.f32 "
        "{%0,%1,%2,%3}, {%4,%5,%6,%7}, {%8,%9}, {%0,%1,%2,%3};"
        : "+f"(c[0]), "+f"(c[1]), "+f"(c[2]), "+f"(c[3])
        : "r"(a[0]), "r"(a[1]), "r"(a[2]), "r"(a[3]), "r"(b[0]), "r"(b[1]));
}

// ---------------------------------------------------------------------------
// LayerNorm: one block per row of 1024
// ---------------------------------------------------------------------------
__global__ __launch_bounds__(256) void ln_kernel(
    const float* __restrict__ x, const float* __restrict__ gamma,
    const float* __restrict__ beta, float* __restrict__ out)
{
    int row = blockIdx.x, tid = threadIdx.x;
    const float4 v = reinterpret_cast<const float4*>(x + (size_t)row*DIMN)[tid];
    float s  = v.x + v.y + v.z + v.w;
    float sq = v.x*v.x + v.y*v.y + v.z*v.z + v.w*v.w;
    #pragma unroll
    for (int off = 16; off; off >>= 1) {
        s  += __shfl_xor_sync(0xffffffffu, s,  off);
        sq += __shfl_xor_sync(0xffffffffu, sq, off);
    }
    __shared__ float rs[8], rq[8];
    int w = tid >> 5, ln = tid & 31;
    if (ln == 0) { rs[w] = s; rq[w] = sq; }
    __syncthreads();
    s = 0.f; sq = 0.f;
    #pragma unroll
    for (int i = 0; i < 8; i++) { s += rs[i]; sq += rq[i]; }
    float mean = s * (1.f/DIMN);
    float var  = sq * (1.f/DIMN) - mean*mean;
    float rstd = rsqrtf(var + 1e-5f);
    float4 gv = reinterpret_cast<const float4*>(gamma)[tid];
    float4 bv = reinterpret_cast<const float4*>(beta)[tid];
    float4 r;
    r.x = (v.x-mean)*rstd*gv.x + bv.x;
    r.y = (v.y-mean)*rstd*gv.y + bv.y;
    r.z = (v.z-mean)*rstd*gv.z + bv.z;
    r.w = (v.w-mean)*rstd*gv.w + bv.w;
    reinterpret_cast<float4*>(out + (size_t)row*DIMN)[tid] = r;
}

// ---------------------------------------------------------------------------
// 3xTF32 mma.sync GEMM (NT) -- unchanged from R5 (passing).
// ---------------------------------------------------------------------------
#define SPAD 36
#define MM_SMEM (4*128*SPAD*4)     // 73728 B

template<bool ADD>
__global__ __launch_bounds__(256, 2)
void mm_mma(const float* __restrict__ A, const float* __restrict__ Bm,
            const float* __restrict__ Cin, float* __restrict__ C,
            int M, int N, int K)
{
    extern __shared__ uint32_t sm4[];
    uint32_t* Ah = sm4;
    uint32_t* Al = Ah + 128*SPAD;
    uint32_t* Bh = Al + 128*SPAD;
    uint32_t* Bl = Bh + 128*SPAD;

    const int tid  = threadIdx.x;
    const int warp = tid >> 5, lane = tid & 31;
    const int g = lane >> 2, t4 = lane & 3;
    const int wm = (warp >> 2) * 64;
    const int wn = (warp & 3) * 32;
    const int rowBase = blockIdx.y * 128;
    const int colBase = blockIdx.x * 128;

    float acc[4][4][4];
    #pragma unroll
    for (int i = 0; i < 4; i++)
        #pragma unroll
        for (int j = 0; j < 4; j++)
            #pragma unroll
            for (int q = 0; q < 4; q++) acc[i][j][q] = 0.f;

    const int NKB = K >> 5;
    for (int kb = 0; kb < NKB; kb++) {
        __syncthreads();
        #pragma unroll
        for (int i = 0; i < 2; i++) {
            int c = i*256 + tid;
            int r = c & 127, q = c >> 7;
            {
                const float* src = A + (size_t)(rowBase + r)*K + kb*32 + q*8;
                float4 v0 = *reinterpret_cast<const float4*>(src);
                float4 v1 = *reinterpret_cast<const float4*>(src + 4);
                uint4 h0, h1, l0, l1;
                split2(v0.x, h0.x, l0.x); split2(v0.y, h0.y, l0.y);
                split2(v0.z, h0.z, l0.z); split2(v0.w, h0.w, l0.w);
                split2(v1.x, h1.x, l1.x); split2(v1.y, h1.y, l1.y);
                split2(v1.z, h1.z, l1.z); split2(v1.w, h1.w, l1.w);
                int o = r*SPAD + q*8;
                *reinterpret_cast<uint4*>(Ah + o)     = h0;
                *reinterpret_cast<uint4*>(Ah + o + 4) = h1;
                *reinterpret_cast<uint4*>(Al + o)     = l0;
                *reinterpret_cast<uint4*>(Al + o + 4) = l1;
            }
            {
                const float* src = Bm + (size_t)(colBase + r)*K + kb*32 + q*8;
                float4 v0 = *reinterpret_cast<const float4*>(src);
                float4 v1 = *reinterpret_cast<const float4*>(src + 4);
                uint4 h0, h1, l0, l1;
                split2(v0.x, h0.x, l0.x); split2(v0.y, h0.y, l0.y);
                split2(v0.z, h0.z, l0.z); split2(v0.w, h0.w, l0.w);
                split2(v1.x, h1.x, l1.x); split2(v1.y, h1.y, l1.y);
                split2(v1.z, h1.z, l1.z); split2(v1.w, h1.w, l1.w);
                int o = r*SPAD + q*8;
                *reinterpret_cast<uint4*>(Bh + o)     = h0;
                *reinterpret_cast<uint4*>(Bh + o + 4) = h1;
                *reinterpret_cast<uint4*>(Bl + o)     = l0;
                *reinterpret_cast<uint4*>(Bl + o + 4) = l1;
            }
        }
        __syncthreads();

        #pragma unroll
        for (int kk = 0; kk < 4; kk++) {
            const int k0 = kk*8 + t4;
            uint32_t bh[4][2], bl[4][2];
            #pragma unroll
            for (int nt = 0; nt < 4; nt++) {
                int nrow = wn + nt*8 + g;
                bh[nt][0] = Bh[nrow*SPAD + k0];
                bh[nt][1] = Bh[nrow*SPAD + k0 + 4];
                bl[nt][0] = Bl[nrow*SPAD + k0];
                bl[nt][1] = Bl[nrow*SPAD + k0 + 4];
            }
            #pragma unroll
            for (int mt = 0; mt < 4; mt++) {
                int r0 = (wm + mt*16 + g)*SPAD;
                int r8 = (wm + mt*16 + 8 + g)*SPAD;
                uint32_t ah[4], al[4];
                ah[0] = Ah[r0 + k0];  ah[1] = Ah[r8 + k0];
                ah[2] = Ah[r0 + k0 + 4];  ah[3] = Ah[r8 + k0 + 4];
                al[0] = Al[r0 + k0];  al[1] = Al[r8 + k0];
                al[2] = Al[r0 + k0 + 4];  al[3] = Al[r8 + k0 + 4];
                #pragma unroll
                for (int nt = 0; nt < 4; nt++) {
                    mma_tf32(acc[mt][nt], ah, bh[nt]);
                    mma_tf32(acc[mt][nt], ah, bl[nt]);
                    mma_tf32(acc[mt][nt], al, bh[nt]);
                }
            }
        }
    }

    #pragma unroll
    for (int mt = 0; mt < 4; mt++) {
        int row0 = rowBase + wm + mt*16 + g;
        #pragma unroll
        for (int nt = 0; nt < 4; nt++) {
            int col = colBase + wn + nt*8 + t4*2;
            size_t o0 = (size_t)row0*N + col;
            size_t o1 = (size_t)(row0 + 8)*N + col;
            float2 v0 = make_float2(acc[mt][nt][0], acc[mt][nt][1]);
            float2 v1 = make_float2(acc[mt][nt][2], acc[mt][nt][3]);
            if (ADD) {
                float2 c0 = *reinterpret_cast<const float2*>(Cin + o0);
                float2 c1 = *reinterpret_cast<const float2*>(Cin + o1);
                v0.x += c0.x; v0.y += c0.y;
                v1.x += c1.x; v1.y += c1.y;
            }
            *reinterpret_cast<float2*>(C + o0) = v0;
            *reinterpret_cast<float2*>(C + o1) = v1;
        }
    }
}

// ---------------------------------------------------------------------------
// GEGLU branch: branch[:, 0:1024] = lin * gelu_exact(pre)
// ---------------------------------------------------------------------------
__device__ __forceinline__ float gelu_exact(float v) {
    return 0.5f * v * (1.f + erff(v * 0.70710678118654752440f));
}
__global__ __launch_bounds__(256) void glu_kernel(
    const float* __restrict__ proj, float* __restrict__ branch)
{
    int idx = blockIdx.x * 256 + threadIdx.x;
    int r  = idx >> 8;
    int c4 = idx & 255;
    float4 lin = *reinterpret_cast<const float4*>(&proj[(size_t)r*NPROJ + 3*DIMN + c4*4]);
    float4 pre = *reinterpret_cast<const float4*>(&proj[(size_t)r*NPROJ + 4*DIMN + c4*4]);
    float4 o;
    o.x = lin.x * gelu_exact(pre.x);
    o.y = lin.y * gelu_exact(pre.y);
    o.z = lin.z * gelu_exact(pre.z);
    o.w = lin.w * gelu_exact(pre.w);
    *reinterpret_cast<float4*>(&branch[(size_t)r*NBR + c4*4]) = o;
}

// ---------------------------------------------------------------------------
// Flash attention (causal, power-softmax p=2) on mma.sync tf32 (3-term split).
// BQ=BK=64, hd=128, 256 threads = 8 warps: warp (wm = (w>>1)*16 rows,
// wn = w&1 halves of cols). S via QhKh+QhKl+QlKh; PV via PhVh+PhVl+PlVh.
// K/V pre-split into hi/lo smem tiles at load. Per-row online state in smem.
//   out = [sum exp(s-m) v] * rsqrt(sum exp(2(s-m)))
// ---------------------------------------------------------------------------
#define QS 132          // Q/K/V smem row stride (words): banks (4g+t4) clean
#define PS 68           // P smem row stride
#define AT_SMEM ((5*64*QS + 64*PS + 64 + 64 + 128 + 128) * 4)   // 187904 B

__global__ __launch_bounds__(256, 1) void attn_mma(
    const float* __restrict__ proj, float* __restrict__ branch)
{
    extern __shared__ float sm[];
    float*    Qs = sm;                               // [64][QS] f32
    uint32_t* Kh = reinterpret_cast<uint32_t*>(sm + 64*QS);
    uint32_t* Kl = Kh + 64*QS;
    uint32_t* Vh = Kl + 64*QS;
    uint32_t* Vl = Vh + 64*QS;
    float*    Ps = sm + 5*64*QS;                     // [64][PS] f32
    float*    row_m  = Ps + 64*PS;                   // [64]
    float*    row_s2 = row_m + 64;                   // [64]
    float*    pmax   = row_s2 + 64;                  // [64][2]
    float*    ps2s   = pmax + 128;                   // [64][2]

    const int tid = threadIdx.x;
    const int warp = tid >> 5, lane = tid & 31;
    const int g = lane >> 2, t4 = lane & 3;
    const int wm = (warp >> 1) * 16;     // row base within 64
    const int wn = warp & 1;             // col half
    const int qb = blockIdx.x;
    const int bh = blockIdx.y;
    const int b = bh >> 3, h = bh & 7;
    const float scale = 0.08838834764831845f;   // 1/sqrt(128)

    const size_t rowOff = (size_t)(b * SEQL) * NPROJ;
    const int colQ = h*HDIM, colK = DIMN + h*HDIM, colV = 2*DIMN + h*HDIM;

    // Load Q tile [64][128] (f32; A-operand split happens at fragment load)
    #pragma unroll
    for (int i = 0; i < 8; i++) {
        int idx4 = tid + i*256;
        int r = idx4 >> 5, d4 = idx4 & 31;
        float4 v = *reinterpret_cast<const float4*>(
            &proj[rowOff + (size_t)(qb*64 + r)*NPROJ + colQ + d4*4]);
        *reinterpret_cast<float4*>(&Qs[r*QS + d4*4]) = v;
    }
    if (tid < 64) { row_m[tid] = -INFINITY; row_s2[tid] = 0.f; }

    float O[8][4];
    #pragma unroll
    for (int i = 0; i < 8; i++)
        #pragma unroll
        for (int q = 0; q < 4; q++) O[i][q] = 0.f;

    for (int kb = 0; kb <= qb; kb++) {
        __syncthreads();    // prev PV done reading Vs/Ps; state writes done
        // Load + split K, V tiles into hi/lo smem
        #pragma unroll
        for (int i = 0; i < 8; i++) {
            int idx4 = tid + i*256;
            int r = idx4 >> 5, d4 = idx4 & 31;
            float4 kv = *reinterpret_cast<const float4*>(
                &proj[rowOff + (size_t)(kb*64 + r)*NPROJ + colK + d4*4]);
            float4 vv = *reinterpret_cast<const float4*>(
                &proj[rowOff + (size_t)(kb*64 + r)*NPROJ + colV + d4*4]);
            uint4 hh, ll;
            int o = r*QS + d4*4;
            split2(kv.x, hh.x, ll.x); split2(kv.y, hh.y, ll.y);
            split2(kv.z, hh.z, ll.z); split2(kv.w, hh.w, ll.w);
            *reinterpret_cast<uint4*>(Kh + o) = hh;
            *reinterpret_cast<uint4*>(Kl + o) = ll;
            split2(vv.x, hh.x, ll.x); split2(vv.y, hh.y, ll.y);
            split2(vv.z, hh.z, ll.z); split2(vv.w, hh.w, ll.w);
            *reinterpret_cast<uint4*>(Vh + o) = hh;
            *reinterpret_cast<uint4*>(Vl + o) = ll;
        }
        __syncthreads();

        // ---- S = Q K^T (warp tile 16x32: 4 n-tiles; 16 k8 steps; 3x split)
        float s[4][4];
        #pragma unroll
        for (int nt = 0; nt < 4; nt++)
            #pragma unroll
            for (int q = 0; q < 4; q++) s[nt][q] = 0.f;
        #pragma unroll
        for (int kk = 0; kk < 16; kk++) {
            const int k0 = kk*8 + t4;
            uint32_t ah[4], al[4];
            split2(Qs[(wm + g    )*QS + k0    ], ah[0], al[0]);
            split2(Qs[(wm + g + 8)*QS + k0    ], ah[1], al[1]);
            split2(Qs[(wm + g    )*QS + k0 + 4], ah[2], al[2]);
            split2(Qs[(wm + g + 8)*QS + k0 + 4], ah[3], al[3]);
            #pragma unroll
            for (int nt = 0; nt < 4; nt++) {
                int krow = (wn*32 + nt*8 + g)*QS;
                uint32_t bhf[2] = { Kh[krow + k0], Kh[krow + k0 + 4] };
                uint32_t blf[2] = { Kl[krow + k0], Kl[krow + k0 + 4] };
                mma_tf32(s[nt], ah, bhf);
                mma_tf32(s[nt], ah, blf);
                mma_tf32(s[nt], al, bhf);
            }
        }

        // ---- scale + causal mask + row max (local)
        const bool diag = (kb == qb);
        float lmax[2] = { -INFINITY, -INFINITY };
        #pragma unroll
        for (int nt = 0; nt < 4; nt++)
            #pragma unroll
            for (int q = 0; q < 4; q++) {
                int ri = q >> 1, ci = q & 1;
                float v = s[nt][q] * scale;
                if (diag) {
                    int qg = wm + g + 8*ri;
                    int kg = wn*32 + nt*8 + 2*t4 + ci;
                    if (kg > qg) v = -INFINITY;
                }
                s[nt][q] = v;
                lmax[ri] = fmaxf(lmax[ri], v);
            }
        #pragma unroll
        for (int off = 1; off < 4; off <<= 1) {
            lmax[0] = fmaxf(lmax[0], __shfl_xor_sync(0xffffffffu, lmax[0], off));
            lmax[1] = fmaxf(lmax[1], __shfl_xor_sync(0xffffffffu, lmax[1], off));
        }
        if (t4 == 0) {
            pmax[(wm + g    )*2 + wn] = lmax[0];
            pmax[(wm + g + 8)*2 + wn] = lmax[1];
        }
        __syncthreads();

        // ---- online p=2 softmax update
        float mn[2], corr[2], lsum[2];
        #pragma unroll
        for (int ri = 0; ri < 2; ri++) {
            int row = wm + g + 8*ri;
            float mo = row_m[row];
            float tm = fmaxf(pmax[row*2], pmax[row*2 + 1]);
            mn[ri] = fmaxf(mo, tm);
            corr[ri] = __expf(mo - mn[ri]);
            lsum[ri] = 0.f;
        }
        #pragma unroll
        for (int nt = 0; nt < 4; nt++) {
            #pragma unroll
            for (int q = 0; q < 4; q++) {
                int ri = q >> 1;
                float p = __expf(s[nt][q] - mn[ri]);
                s[nt][q] = p;
                lsum[ri] += p * p;
            }
            *reinterpret_cast<float2*>(&Ps[(wm + g    )*PS + wn*32 + nt*8 + 2*t4]) =
                make_float2(s[nt][0], s[nt][1]);
            *reinterpret_cast<float2*>(&Ps[(wm + g + 8)*PS + wn*32 + nt*8 + 2*t4]) =
                make_float2(s[nt][2], s[nt][3]);
        }
        #pragma unroll
        for (int off = 1; off < 4; off <<= 1) {
            lsum[0] += __shfl_xor_sync(0xffffffffu, lsum[0], off);
            lsum[1] += __shfl_xor_sync(0xffffffffu, lsum[1], off);
        }
        if (t4 == 0) {
            ps2s[(wm + g    )*2 + wn] = lsum[0];
            ps2s[(wm + g + 8)*2 + wn] = lsum[1];
        }
        // rescale O by corr (rows match this warp's m rows)
        #pragma unroll
        for (int nt = 0; nt < 8; nt++)
            #pragma unroll
            for (int q = 0; q < 4; q++) O[nt][q] *= corr[q >> 1];
        __syncthreads();

        if (wn == 0 && t4 == 0) {
            #pragma unroll
            for (int ri = 0; ri < 2; ri++) {
                int row = wm + g + 8*ri;
                row_s2[row] = row_s2[row]*corr[ri]*corr[ri]
                            + ps2s[row*2] + ps2s[row*2 + 1];
                row_m[row] = mn[ri];
            }
        }

        // ---- O += P V (warp tile 16x64: 8 n-tiles; 8 k8 steps; 3x split)
        #pragma unroll
        for (int kk = 0; kk < 8; kk++) {
            const int k0 = kk*8 + t4;
            uint32_t ah[4], al[4];
            split2(Ps[(wm + g    )*PS + k0    ], ah[0], al[0]);
            split2(Ps[(wm + g + 8)*PS + k0    ], ah[1], al[1]);
            split2(Ps[(wm + g    )*PS + k0 + 4], ah[2], al[2]);
            split2(Ps[(wm + g + 8)*PS + k0 + 4], ah[3], al[3]);
            #pragma unroll
            for (int nt = 0; nt < 8; nt++) {
                int dcol = wn*64 + nt*8 + g;
                uint32_t bhf[2] = { Vh[k0*QS + dcol], Vh[(k0 + 4)*QS + dcol] };
                uint32_t blf[2] = { Vl[k0*QS + dcol], Vl[(k0 + 4)*QS + dcol] };
                mma_tf32(O[nt], ah, bhf);
                mma_tf32(O[nt], ah, blf);
                mma_tf32(O[nt], al, bhf);
            }
        }
    }

    __syncthreads();    // row_s2 final updates visible to all warps
    float inv[2];
    inv[0] = rsqrtf(row_s2[wm + g]);
    inv[1] = rsqrtf(row_s2[wm + g + 8]);

    #pragma unroll
    for (int ri = 0; ri < 2; ri++) {
        int rg = b*SEQL + qb*64 + wm + g + 8*ri;
        size_t base = (size_t)rg*NBR + DIMN + h*HDIM + wn*64 + 2*t4;
        #pragma unroll
        for (int nt = 0; nt < 8; nt++) {
            float2 v = make_float2(O[nt][2*ri] * inv[ri], O[nt][2*ri + 1] * inv[ri]);
            *reinterpret_cast<float2*>(&branch[base + nt*8]) = v;
        }
    }
}

// ---------------------------------------------------------------------------
// Launch
// ---------------------------------------------------------------------------
extern "C" void kernel_launch(void* const* d_in, const int* in_sizes, int n_in,
                              void* d_out, int out_size)
{
    const float* x     = (const float*)d_in[0];
    const float* gamma = (const float*)d_in[1];
    const float* beta  = (const float*)d_in[2];
    const float* w_qkv = (const float*)d_in[3];
    const float* w_out = (const float*)d_in[4];
    float* out = (float*)d_out;

    float *hbuf, *projbuf, *branchbuf;
    cudaGetSymbolAddress((void**)&hbuf,      g_h);
    cudaGetSymbolAddress((void**)&projbuf,   g_proj);
    cudaGetSymbolAddress((void**)&branchbuf, g_branch);

    cudaFuncSetAttribute(attn_mma, cudaFuncAttributeMaxDynamicSharedMemorySize, AT_SMEM);
    cudaFuncSetAttribute(mm_mma<false>, cudaFuncAttributeMaxDynamicSharedMemorySize, MM_SMEM);
    cudaFuncSetAttribute(mm_mma<true>,  cudaFuncAttributeMaxDynamicSharedMemorySize, MM_SMEM);

    // 1) LayerNorm
    ln_kernel<<<NROWS, 256>>>(x, gamma, beta, hbuf);

    // 2) proj = h @ w_qkv^T   [8192 x 5120], K=1024  (3xTF32 mma.sync)
    {
        dim3 grid(NPROJ/128, NROWS/128);
        mm_mma<false><<<grid, 256, MM_SMEM>>>(hbuf, w_qkv, nullptr, projbuf,
                                              NROWS, NPROJ, DIMN);
    }

    // 3) GEGLU half of branch
    glu_kernel<<<(NROWS*DIMN)/4/256, 256>>>(projbuf, branchbuf);

    // 4) Attention half of branch (tensor-core flash attention)
    {
        dim3 grid(SEQL/64, BATCH*NHEADS);
        attn_mma<<<grid, 256, AT_SMEM>>>(projbuf, branchbuf);
    }

    // 5) out = x + branch @ w_out^T   [8192 x 1024], K=2048  (3xTF32 mma.sync)
    {
        dim3 grid(DIMN/128, NROWS/128);
        mm_mma<true><<<grid, 256, MM_SMEM>>>(branchbuf, w_out, x, out,
                                             NROWS, DIMN, NBR);
    }
}

// round 9
// speedup vs baseline: 3.6585x; 2.2113x over previous
#include <cuda_runtime.h>
#include <math.h>
#include <stdint.h>

// Problem constants
#define DIMN 1024
#define SEQL 2048
#define BATCH 4
#define NHEADS 8
#define HDIM 128
#define NROWS (BATCH*SEQL)   // 8192
#define NPROJ (5*DIMN)       // 5120
#define NBR (2*DIMN)         // 2048

// Scratch (static __device__ arrays -- allocation-free per harness rules)
__device__ float g_h[(size_t)NROWS*DIMN];       // LayerNorm output
__device__ float g_proj[(size_t)NROWS*NPROJ];   // qkv+lin+pre projection
__device__ float g_branch[(size_t)NROWS*NBR];   // [geglu | attn]

// ===========================================================================
// bf16 mma.sync helpers (3xBF16 split: D += AhBh + AhBl + AlBh)
// ===========================================================================
__device__ __forceinline__ uint32_t pack_bf16(float e, float o) {
    // lower 16 bits = e (even k), upper = o (odd k)
    uint32_t r;
    asm("cvt.rn.bf16x2.f32 %0, %1, %2;" : "=r"(r) : "f"(o), "f"(e));
    return r;
}
__device__ __forceinline__ float lofl(uint32_t p){ return __uint_as_float(p << 16); }
__device__ __forceinline__ float hifl(uint32_t p){ return __uint_as_float(p & 0xFFFF0000u); }

__device__ __forceinline__ void split8(float4 v0, float4 v1, uint4& h, uint4& l) {
    h.x = pack_bf16(v0.x, v0.y);
    h.y = pack_bf16(v0.z, v0.w);
    h.z = pack_bf16(v1.x, v1.y);
    h.w = pack_bf16(v1.z, v1.w);
    l.x = pack_bf16(v0.x - lofl(h.x), v0.y - hifl(h.x));
    l.y = pack_bf16(v0.z - lofl(h.y), v0.w - hifl(h.y));
    l.z = pack_bf16(v1.x - lofl(h.z), v1.y - hifl(h.z));
    l.w = pack_bf16(v1.z - lofl(h.w), v1.w - hifl(h.w));
}

__device__ __forceinline__ void mma_bf16(float* c, const uint32_t* a,
                                         const uint32_t* b) {
    asm volatile(
        "mma.sync.aligned.m16n8k16.row.col.f32.bf16.bf16.f32 "
        "{%0,%1,%2,%3}, {%4,%5,%6,%7}, {%8,%9}, {%0,%1,%2,%3};"
        : "+f"(c[0]), "+f"(c[1]), "+f"(c[2]), "+f"(c[3])
        : "r"(a[0]), "r"(a[1]), "r"(a[2]), "r"(a[3]), "r"(b[0]), "r"(b[1]));
}

// ---------------------------------------------------------------------------
// LayerNorm: one block per row of 1024
// ---------------------------------------------------------------------------
__global__ __launch_bounds__(256) void ln_kernel(
    const float* __restrict__ x, const float* __restrict__ gamma,
    const float* __restrict__ beta, float* __restrict__ out)
{
    int row = blockIdx.x, tid = threadIdx.x;
    const float4 v = reinterpret_cast<const float4*>(x + (size_t)row*DIMN)[tid];
    float s  = v.x + v.y + v.z + v.w;
    float sq = v.x*v.x + v.y*v.y + v.z*v.z + v.w*v.w;
    #pragma unroll
    for (int off = 16; off; off >>= 1) {
        s  += __shfl_xor_sync(0xffffffffu, s,  off);
        sq += __shfl_xor_sync(0xffffffffu, sq, off);
    }
    __shared__ float rs[8], rq[8];
    int w = tid >> 5, ln = tid & 31;
    if (ln == 0) { rs[w] = s; rq[w] = sq; }
    __syncthreads();
    s = 0.f; sq = 0.f;
    #pragma unroll
    for (int i = 0; i < 8; i++) { s += rs[i]; sq += rq[i]; }
    float mean = s * (1.f/DIMN);
    float var  = sq * (1.f/DIMN) - mean*mean;
    float rstd = rsqrtf(var + 1e-5f);
    float4 gv = reinterpret_cast<const float4*>(gamma)[tid];
    float4 bv = reinterpret_cast<const float4*>(beta)[tid];
    float4 r;
    r.x = (v.x-mean)*rstd*gv.x + bv.x;
    r.y = (v.y-mean)*rstd*gv.y + bv.y;
    r.z = (v.z-mean)*rstd*gv.z + bv.z;
    r.w = (v.w-mean)*rstd*gv.w + bv.w;
    reinterpret_cast<float4*>(out + (size_t)row*DIMN)[tid] = r;
}

// ---------------------------------------------------------------------------
// 3xBF16 mma.sync GEMM (NT): C[M,N] = A[M,K] @ B[N,K]^T (+ optional Cin)
// CTA 128x128, BK=32, 8 warps (2x4) of 64x32 warp tiles.
// bf16 pairs packed in u32; rows of 16 u32 with XOR swizzle on uint4 groups:
// phys_group = c ^ ((r>>1)&3). Loads and stores conflict-free.
// ---------------------------------------------------------------------------
#define MM_SMEM (4*128*16*4)     // 32768 B

template<bool ADD>
__global__ __launch_bounds__(256, 2)
void mm_bf3(const float* __restrict__ A, const float* __restrict__ Bm,
            const float* __restrict__ Cin, float* __restrict__ C,
            int M, int N, int K)
{
    extern __shared__ uint32_t smu[];
    uint32_t* Ah = smu;              // [128][16]
    uint32_t* Al = Ah + 128*16;
    uint32_t* Bh = Al + 128*16;
    uint32_t* Bl = Bh + 128*16;

    const int tid  = threadIdx.x;
    const int warp = tid >> 5, lane = tid & 31;
    const int g = lane >> 2, t4 = lane & 3;
    const int wm = (warp >> 2) * 64;
    const int wn = (warp & 3) * 32;
    const int rowBase = blockIdx.y * 128;
    const int colBase = blockIdx.x * 128;

    float acc[4][4][4];
    #pragma unroll
    for (int i = 0; i < 4; i++)
        #pragma unroll
        for (int j = 0; j < 4; j++)
            #pragma unroll
            for (int q = 0; q < 4; q++) acc[i][j][q] = 0.f;

    const int NKB = K >> 5;
    for (int kb = 0; kb < NKB; kb++) {
        __syncthreads();
        #pragma unroll
        for (int i = 0; i < 2; i++) {
            int linear = i*256 + tid;
            int r = linear >> 2, c = linear & 3;    // row, k8-group
            int pg = (c ^ ((r >> 1) & 3)) * 4;
            {
                const float* src = A + (size_t)(rowBase + r)*K + kb*32 + c*8;
                float4 v0 = *reinterpret_cast<const float4*>(src);
                float4 v1 = *reinterpret_cast<const float4*>(src + 4);
                uint4 h, l; split8(v0, v1, h, l);
                *reinterpret_cast<uint4*>(Ah + r*16 + pg) = h;
                *reinterpret_cast<uint4*>(Al + r*16 + pg) = l;
            }
            {
                const float* src = Bm + (size_t)(colBase + r)*K + kb*32 + c*8;
                float4 v0 = *reinterpret_cast<const float4*>(src);
                float4 v1 = *reinterpret_cast<const float4*>(src + 4);
                uint4 h, l; split8(v0, v1, h, l);
                *reinterpret_cast<uint4*>(Bh + r*16 + pg) = h;
                *reinterpret_cast<uint4*>(Bl + r*16 + pg) = l;
            }
        }
        __syncthreads();

        #pragma unroll
        for (int kk = 0; kk < 2; kk++) {
            uint32_t bhf[4][2], blf[4][2];
            #pragma unroll
            for (int nt = 0; nt < 4; nt++) {
                int n = wn + nt*8 + g;
                int s = (n >> 1) & 3;
                int c0 = ((2*kk)   ^ s)*4 + t4;
                int c1 = ((2*kk+1) ^ s)*4 + t4;
                bhf[nt][0] = Bh[n*16 + c0];  bhf[nt][1] = Bh[n*16 + c1];
                blf[nt][0] = Bl[n*16 + c0];  blf[nt][1] = Bl[n*16 + c1];
            }
            #pragma unroll
            for (int mt = 0; mt < 4; mt++) {
                int r1 = wm + mt*16 + g;
                int s = (r1 >> 1) & 3;              // same for r1+8
                int c0 = ((2*kk)   ^ s)*4 + t4;
                int c1 = ((2*kk+1) ^ s)*4 + t4;
                uint32_t ah[4], al[4];
                ah[0] = Ah[r1*16 + c0];  ah[1] = Ah[(r1+8)*16 + c0];
                ah[2] = Ah[r1*16 + c1];  ah[3] = Ah[(r1+8)*16 + c1];
                al[0] = Al[r1*16 + c0];  al[1] = Al[(r1+8)*16 + c0];
                al[2] = Al[r1*16 + c1];  al[3] = Al[(r1+8)*16 + c1];
                #pragma unroll
                for (int nt = 0; nt < 4; nt++) {
                    mma_bf16(acc[mt][nt], ah, bhf[nt]);
                    mma_bf16(acc[mt][nt], ah, blf[nt]);
                    mma_bf16(acc[mt][nt], al, bhf[nt]);
                }
            }
        }
    }

    #pragma unroll
    for (int mt = 0; mt < 4; mt++) {
        int row0 = rowBase + wm + mt*16 + g;
        #pragma unroll
        for (int nt = 0; nt < 4; nt++) {
            int col = colBase + wn + nt*8 + t4*2;
            size_t o0 = (size_t)row0*N + col;
            size_t o1 = (size_t)(row0 + 8)*N + col;
            float2 v0 = make_float2(acc[mt][nt][0], acc[mt][nt][1]);
            float2 v1 = make_float2(acc[mt][nt][2], acc[mt][nt][3]);
            if (ADD) {
                float2 c0 = *reinterpret_cast<const float2*>(Cin + o0);
                float2 c1 = *reinterpret_cast<const float2*>(Cin + o1);
                v0.x += c0.x; v0.y += c0.y;
                v1.x += c1.x; v1.y += c1.y;
            }
            *reinterpret_cast<float2*>(C + o0) = v0;
            *reinterpret_cast<float2*>(C + o1) = v1;
        }
    }
}

// ---------------------------------------------------------------------------
// GEGLU branch: branch[:, 0:1024] = lin * gelu_exact(pre)
// ---------------------------------------------------------------------------
__device__ __forceinline__ float gelu_exact(float v) {
    return 0.5f * v * (1.f + erff(v * 0.70710678118654752440f));
}
__global__ __launch_bounds__(256) void glu_kernel(
    const float* __restrict__ proj, float* __restrict__ branch)
{
    int idx = blockIdx.x * 256 + threadIdx.x;
    int r  = idx >> 8;
    int c4 = idx & 255;
    float4 lin = *reinterpret_cast<const float4*>(&proj[(size_t)r*NPROJ + 3*DIMN + c4*4]);
    float4 pre = *reinterpret_cast<const float4*>(&proj[(size_t)r*NPROJ + 4*DIMN + c4*4]);
    float4 o;
    o.x = lin.x * gelu_exact(pre.x);
    o.y = lin.y * gelu_exact(pre.y);
    o.z = lin.z * gelu_exact(pre.z);
    o.w = lin.w * gelu_exact(pre.w);
    *reinterpret_cast<float4*>(&branch[(size_t)r*NBR + c4*4]) = o;
}

// ---------------------------------------------------------------------------
// Flash attention (causal, p=2 power-softmax) on 3xBF16 mma.sync.
// BQ=128, BK=64. 8 warps; warp w owns q-rows w*16..w*16+15 ENTIRELY:
// all softmax state in registers, P stays in registers (S c-frag == PV a-frag).
// Q/K: [rows][64 u32] bf16-pair tiles, XOR-swizzled (phys_group = c ^ (r&7)).
// V: packed pairs along keys: Vp[32 kpairs][128 dims + 8 pad].
//   out = [sum exp(s-m) v] * rsqrt(sum exp(2(s-m)))
// ---------------------------------------------------------------------------
#define ATV 136
#define AT_SMEM ((2*128*64 + 2*64*64 + 2*32*ATV) * 4)   // 133120 B

__global__ __launch_bounds__(256, 1) void attn_bf3(
    const float* __restrict__ proj, float* __restrict__ branch)
{
    extern __shared__ uint32_t su[];
    uint32_t* Qh = su;               // [128][64]
    uint32_t* Ql = Qh + 128*64;
    uint32_t* Kh = Ql + 128*64;      // [64][64]
    uint32_t* Kl = Kh + 64*64;
    uint32_t* Vh = Kl + 64*64;       // [32][ATV]
    uint32_t* Vl = Vh + 32*ATV;

    const int tid = threadIdx.x;
    const int warp = tid >> 5, lane = tid & 31;
    const int g = lane >> 2, t4 = lane & 3;
    const int wm = warp * 16;
    const int qb = (SEQL/128 - 1) - blockIdx.x;     // big tiles first
    const int bh = blockIdx.y;
    const int b = bh >> 3, h = bh & 7;
    const float scale = 0.08838834764831845f;       // 1/sqrt(128)

    const size_t rowOff = (size_t)(b * SEQL) * NPROJ;
    const int colQ = h*HDIM, colK = DIMN + h*HDIM, colV = 2*DIMN + h*HDIM;

    // ---- load + split Q [128][128] into bf16-pair hi/lo tiles
    #pragma unroll
    for (int it = 0; it < 8; it++) {
        int linear = it*256 + tid;
        int r = linear >> 4, c = linear & 15;
        const float* src = &proj[rowOff + (size_t)(qb*128 + r)*NPROJ + colQ + c*8];
        float4 v0 = *reinterpret_cast<const float4*>(src);
        float4 v1 = *reinterpret_cast<const float4*>(src + 4);
        uint4 hh, ll; split8(v0, v1, hh, ll);
        int pg = (c ^ (r & 7)) * 4;
        *reinterpret_cast<uint4*>(Qh + r*64 + pg) = hh;
        *reinterpret_cast<uint4*>(Ql + r*64 + pg) = ll;
    }

    float m[2]  = { -INFINITY, -INFINITY };
    float S2[2] = { 0.f, 0.f };
    float O[16][4];
    #pragma unroll
    for (int i = 0; i < 16; i++)
        #pragma unroll
        for (int q = 0; q < 4; q++) O[i][q] = 0.f;

    const int qg0 = qb*128 + wm + g;     // this thread's first row (global)
    const int KT = 2*qb + 2;

    for (int kb = 0; kb < KT; kb++) {
        __syncthreads();
        // ---- load + split K tile [64][128]
        #pragma unroll
        for (int it = 0; it < 4; it++) {
            int linear = it*256 + tid;
            int r = linear >> 4, c = linear & 15;
            const float* src = &proj[rowOff + (size_t)(kb*64 + r)*NPROJ + colK + c*8];
            float4 v0 = *reinterpret_cast<const float4*>(src);
            float4 v1 = *reinterpret_cast<const float4*>(src + 4);
            uint4 hh, ll; split8(v0, v1, hh, ll);
            int pg = (c ^ (r & 7)) * 4;
            *reinterpret_cast<uint4*>(Kh + r*64 + pg) = hh;
            *reinterpret_cast<uint4*>(Kl + r*64 + pg) = ll;
        }
        // ---- load + split V tile, packed pairs along keys: Vp[kp][dim]
        #pragma unroll
        for (int it = 0; it < 4; it++) {
            int kp = it*8 + (tid >> 5);
            int dbase = (tid & 31) * 4;
            const float* se = &proj[rowOff + (size_t)(kb*64 + 2*kp    )*NPROJ + colV + dbase];
            const float* so = &proj[rowOff + (size_t)(kb*64 + 2*kp + 1)*NPROJ + colV + dbase];
            float4 e = *reinterpret_cast<const float4*>(se);
            float4 o = *reinterpret_cast<const float4*>(so);
            uint4 hh, ll;
            hh.x = pack_bf16(e.x, o.x); ll.x = pack_bf16(e.x - lofl(hh.x), o.x - hifl(hh.x));
            hh.y = pack_bf16(e.y, o.y); ll.y = pack_bf16(e.y - lofl(hh.y), o.y - hifl(hh.y));
            hh.z = pack_bf16(e.z, o.z); ll.z = pack_bf16(e.z - lofl(hh.z), o.z - hifl(hh.z));
            hh.w = pack_bf16(e.w, o.w); ll.w = pack_bf16(e.w - lofl(hh.w), o.w - hifl(hh.w));
            *reinterpret_cast<uint4*>(Vh + kp*ATV + dbase) = hh;
            *reinterpret_cast<uint4*>(Vl + kp*ATV + dbase) = ll;
        }
        __syncthreads();

        if (kb*64 > qb*128 + wm + 15) continue;     // tile fully masked for warp

        // ---- S = Q K^T : warp tile 16x64, 8 k16 steps, 3xBF16
        float s[8][4];
        #pragma unroll
        for (int nt = 0; nt < 8; nt++)
            #pragma unroll
            for (int q = 0; q < 4; q++) s[nt][q] = 0.f;
        #pragma unroll 2
        for (int kk = 0; kk < 8; kk++) {
            int c0 = ((2*kk)   ^ g)*4 + t4;
            int c1 = ((2*kk+1) ^ g)*4 + t4;
            uint32_t ah[4], al[4];
            ah[0] = Qh[(wm+g  )*64 + c0];  ah[1] = Qh[(wm+8+g)*64 + c0];
            ah[2] = Qh[(wm+g  )*64 + c1];  ah[3] = Qh[(wm+8+g)*64 + c1];
            al[0] = Ql[(wm+g  )*64 + c0];  al[1] = Ql[(wm+8+g)*64 + c0];
            al[2] = Ql[(wm+g  )*64 + c1];  al[3] = Ql[(wm+8+g)*64 + c1];
            #pragma unroll
            for (int nt = 0; nt < 8; nt++) {
                int n = nt*8 + g;                    // (n & 7) == g: same c0/c1
                uint32_t bh2[2] = { Kh[n*64 + c0], Kh[n*64 + c1] };
                uint32_t bl2[2] = { Kl[n*64 + c0], Kl[n*64 + c1] };
                mma_bf16(s[nt], ah, bh2);
                mma_bf16(s[nt], ah, bl2);
                mma_bf16(s[nt], al, bh2);
            }
        }

        // ---- scale + causal mask + warp-local row max
        float lmax[2] = { -INFINITY, -INFINITY };
        const bool need_mask = (kb*64 + 63 > qb*128 + wm);   // warp-uniform
        #pragma unroll
        for (int nt = 0; nt < 8; nt++)
            #pragma unroll
            for (int q = 0; q < 4; q++) {
                int ri = q >> 1;
                float v = s[nt][q] * scale;
                if (need_mask) {
                    int kg = kb*64 + nt*8 + 2*t4 + (q & 1);
                    if (kg > qg0 + 8*ri) v = -INFINITY;
                }
                s[nt][q] = v;
                lmax[ri] = fmaxf(lmax[ri], v);
            }
        #pragma unroll
        for (int off = 1; off < 4; off <<= 1) {
            lmax[0] = fmaxf(lmax[0], __shfl_xor_sync(0xffffffffu, lmax[0], off));
            lmax[1] = fmaxf(lmax[1], __shfl_xor_sync(0xffffffffu, lmax[1], off));
        }

        // ---- online p=2 softmax update (all in registers)
        float mn[2], corr[2], lsum[2];
        #pragma unroll
        for (int ri = 0; ri < 2; ri++) {
            mn[ri]   = fmaxf(m[ri], lmax[ri]);
            corr[ri] = __expf(m[ri] - mn[ri]);
            m[ri]    = mn[ri];
            lsum[ri] = 0.f;
        }
        #pragma unroll
        for (int nt = 0; nt < 8; nt++)
            #pragma unroll
            for (int q = 0; q < 4; q++) {
                int ri = q >> 1;
                float p = __expf(s[nt][q] - mn[ri]);
                s[nt][q] = p;
                lsum[ri] += p * p;
            }
        #pragma unroll
        for (int off = 1; off < 4; off <<= 1) {
            lsum[0] += __shfl_xor_sync(0xffffffffu, lsum[0], off);
            lsum[1] += __shfl_xor_sync(0xffffffffu, lsum[1], off);
        }
        #pragma unroll
        for (int ri = 0; ri < 2; ri++)
            S2[ri] = S2[ri]*corr[ri]*corr[ri] + lsum[ri];
        #pragma unroll
        for (int nt = 0; nt < 16; nt++)
            #pragma unroll
            for (int q = 0; q < 4; q++) O[nt][q] *= corr[q >> 1];

        // ---- O += P V : P a-frags built in registers from s; 4 k16 steps
        #pragma unroll
        for (int kk = 0; kk < 4; kk++) {
            uint32_t ph[4], pl[4];
            ph[0] = pack_bf16(s[2*kk][0],   s[2*kk][1]);
            ph[1] = pack_bf16(s[2*kk][2],   s[2*kk][3]);
            ph[2] = pack_bf16(s[2*kk+1][0], s[2*kk+1][1]);
            ph[3] = pack_bf16(s[2*kk+1][2], s[2*kk+1][3]);
            pl[0] = pack_bf16(s[2*kk][0]   - lofl(ph[0]), s[2*kk][1]   - hifl(ph[0]));
            pl[1] = pack_bf16(s[2*kk][2]   - lofl(ph[1]), s[2*kk][3]   - hifl(ph[1]));
            pl[2] = pack_bf16(s[2*kk+1][0] - lofl(ph[2]), s[2*kk+1][1] - hifl(ph[2]));
            pl[3] = pack_bf16(s[2*kk+1][2] - lofl(ph[3]), s[2*kk+1][3] - hifl(ph[3]));
            int vr0 = (kk*8 + t4)*ATV;
            int vr1 = (kk*8 + 4 + t4)*ATV;
            #pragma unroll
            for (int nt = 0; nt < 16; nt++) {
                int n = nt*8 + g;
                uint32_t vbh[2] = { Vh[vr0 + n], Vh[vr1 + n] };
                uint32_t vbl[2] = { Vl[vr0 + n], Vl[vr1 + n] };
                mma_bf16(O[nt], ph, vbh);
                mma_bf16(O[nt], ph, vbl);
                mma_bf16(O[nt], pl, vbh);
            }
        }
    }

    // ---- epilogue: scale by rsqrt(S2), store
    float inv0 = rsqrtf(S2[0]);
    float inv1 = rsqrtf(S2[1]);
    const size_t rg0 = (size_t)(b*SEQL + qb*128 + wm + g);
    const size_t rg1 = rg0 + 8;
    const int cbase = DIMN + h*HDIM + 2*t4;
    #pragma unroll
    for (int nt = 0; nt < 16; nt++) {
        *reinterpret_cast<float2*>(&branch[rg0*NBR + cbase + nt*8]) =
            make_float2(O[nt][0]*inv0, O[nt][1]*inv0);
        *reinterpret_cast<float2*>(&branch[rg1*NBR + cbase + nt*8]) =
            make_float2(O[nt][2]*inv1, O[nt][3]*inv1);
    }
}

// ---------------------------------------------------------------------------
// Launch
// ---------------------------------------------------------------------------
extern "C" void kernel_launch(void* const* d_in, const int* in_sizes, int n_in,
                              void* d_out, int out_size)
{
    const float* x     = (const float*)d_in[0];
    const float* gamma = (const float*)d_in[1];
    const float* beta  = (const float*)d_in[2];
    const float* w_qkv = (const float*)d_in[3];
    const float* w_out = (const float*)d_in[4];
    float* out = (float*)d_out;

    float *hbuf, *projbuf, *branchbuf;
    cudaGetSymbolAddress((void**)&hbuf,      g_h);
    cudaGetSymbolAddress((void**)&projbuf,   g_proj);
    cudaGetSymbolAddress((void**)&branchbuf, g_branch);

    cudaFuncSetAttribute(attn_bf3, cudaFuncAttributeMaxDynamicSharedMemorySize, AT_SMEM);
    cudaFuncSetAttribute(mm_bf3<false>, cudaFuncAttributeMaxDynamicSharedMemorySize, MM_SMEM);
    cudaFuncSetAttribute(mm_bf3<true>,  cudaFuncAttributeMaxDynamicSharedMemorySize, MM_SMEM);

    // 1) LayerNorm
    ln_kernel<<<NROWS, 256>>>(x, gamma, beta, hbuf);

    // 2) proj = h @ w_qkv^T   [8192 x 5120], K=1024  (3xBF16 mma.sync)
    {
        dim3 grid(NPROJ/128, NROWS/128);
        mm_bf3<false><<<grid, 256, MM_SMEM>>>(hbuf, w_qkv, nullptr, projbuf,
                                              NROWS, NPROJ, DIMN);
    }

    // 3) GEGLU half of branch
    glu_kernel<<<(NROWS*DIMN)/4/256, 256>>>(projbuf, branchbuf);

    // 4) Attention half of branch (3xBF16 tensor-core flash attention)
    {
        dim3 grid(SEQL/128, BATCH*NHEADS);
        attn_bf3<<<grid, 256, AT_SMEM>>>(projbuf, branchbuf);
    }

    // 5) out = x + branch @ w_out^T   [8192 x 1024], K=2048  (3xBF16 mma.sync)
    {
        dim3 grid(DIMN/128, NROWS/128);
        mm_bf3<true><<<grid, 256, MM_SMEM>>>(branchbuf, w_out, x, out,
                                             NROWS, DIMN, NBR);
    }
}

// round 10
// speedup vs baseline: 3.7130x; 1.0149x over previous
#include <cuda_runtime.h>
#include <math.h>
#include <stdint.h>

// Problem constants
#define DIMN 1024
#define SEQL 2048
#define BATCH 4
#define NHEADS 8
#define HDIM 128
#define NROWS (BATCH*SEQL)   // 8192
#define NPROJ (5*DIMN)       // 5120
#define NBR (2*DIMN)         // 2048

// Scratch (static __device__ arrays -- allocation-free per harness rules)
// Packed bf16-pair hi/lo arrays: X[r][k/2] u32, lo16=even k, hi16=odd k.
__device__ uint32_t g_hh[(size_t)NROWS*512],  g_hl[(size_t)NROWS*512];   // LN(x)
__device__ uint32_t g_wqh[(size_t)NPROJ*512], g_wql[(size_t)NPROJ*512];  // w_qkv
__device__ uint32_t g_woh[(size_t)DIMN*1024], g_wol[(size_t)DIMN*1024];  // w_out
__device__ uint32_t g_bh[(size_t)NROWS*1024], g_bl[(size_t)NROWS*1024];  // branch
__device__ float    g_proj[(size_t)NROWS*NPROJ];                         // f32 proj

// ===========================================================================
// bf16 helpers (3xBF16 split: D += AhBh + AhBl + AlBh)
// ===========================================================================
__device__ __forceinline__ uint32_t pack_bf16(float e, float o) {
    uint32_t r;
    asm("cvt.rn.bf16x2.f32 %0, %1, %2;" : "=r"(r) : "f"(o), "f"(e));
    return r;
}
__device__ __forceinline__ float lofl(uint32_t p){ return __uint_as_float(p << 16); }
__device__ __forceinline__ float hifl(uint32_t p){ return __uint_as_float(p & 0xFFFF0000u); }

__device__ __forceinline__ void split8(float4 v0, float4 v1, uint4& h, uint4& l) {
    h.x = pack_bf16(v0.x, v0.y);
    h.y = pack_bf16(v0.z, v0.w);
    h.z = pack_bf16(v1.x, v1.y);
    h.w = pack_bf16(v1.z, v1.w);
    l.x = pack_bf16(v0.x - lofl(h.x), v0.y - hifl(h.x));
    l.y = pack_bf16(v0.z - lofl(h.y), v0.w - hifl(h.y));
    l.z = pack_bf16(v1.x - lofl(h.z), v1.y - hifl(h.z));
    l.w = pack_bf16(v1.z - lofl(h.w), v1.w - hifl(h.w));
}

__device__ __forceinline__ void mma_bf16(float* c, const uint32_t* a,
                                         const uint32_t* b) {
    asm volatile(
        "mma.sync.aligned.m16n8k16.row.col.f32.bf16.bf16.f32 "
        "{%0,%1,%2,%3}, {%4,%5,%6,%7}, {%8,%9}, {%0,%1,%2,%3};"
        : "+f"(c[0]), "+f"(c[1]), "+f"(c[2]), "+f"(c[3])
        : "r"(a[0]), "r"(a[1]), "r"(a[2]), "r"(a[3]), "r"(b[0]), "r"(b[1]));
}

__device__ __forceinline__ uint32_t smem_u32(const void* p) {
    uint32_t a;
    asm("{ .reg .u64 t; cvta.to.shared.u64 t, %1; cvt.u32.u64 %0, t; }"
        : "=r"(a) : "l"(p));
    return a;
}
#define CP_ASYNC16(dst, src) \
    asm volatile("cp.async.ca.shared.global [%0], [%1], 16;" \
                 :: "r"(dst), "l"(src) : "memory")
#define CP_COMMIT() asm volatile("cp.async.commit_group;" ::: "memory")
#define CP_WAIT1()  asm volatile("cp.async.wait_group 1;" ::: "memory")
#define CP_WAIT0()  asm volatile("cp.async.wait_group 0;" ::: "memory")

// ---------------------------------------------------------------------------
// Weight split: W[R][K] f32 -> packed pair hi/lo u32 [R][K/2]
// ---------------------------------------------------------------------------
__global__ __launch_bounds__(256) void wsplit_kernel(
    const float* __restrict__ W, uint32_t* __restrict__ Wh,
    uint32_t* __restrict__ Wl)
{
    int idx = blockIdx.x*256 + threadIdx.x;
    float4 v = reinterpret_cast<const float4*>(W)[idx];
    uint32_t h0 = pack_bf16(v.x, v.y), h1 = pack_bf16(v.z, v.w);
    uint32_t l0 = pack_bf16(v.x - lofl(h0), v.y - hifl(h0));
    uint32_t l1 = pack_bf16(v.z - lofl(h1), v.w - hifl(h1));
    reinterpret_cast<uint2*>(Wh)[idx] = make_uint2(h0, h1);
    reinterpret_cast<uint2*>(Wl)[idx] = make_uint2(l0, l1);
}

// ---------------------------------------------------------------------------
// LayerNorm: one block per row of 1024; writes split packed pairs directly.
// ---------------------------------------------------------------------------
__global__ __launch_bounds__(256) void ln_kernel(
    const float* __restrict__ x, const float* __restrict__ gamma,
    const float* __restrict__ beta, uint32_t* __restrict__ hh,
    uint32_t* __restrict__ hl)
{
    int row = blockIdx.x, tid = threadIdx.x;
    const float4 v = reinterpret_cast<const float4*>(x + (size_t)row*DIMN)[tid];
    float s  = v.x + v.y + v.z + v.w;
    float sq = v.x*v.x + v.y*v.y + v.z*v.z + v.w*v.w;
    #pragma unroll
    for (int off = 16; off; off >>= 1) {
        s  += __shfl_xor_sync(0xffffffffu, s,  off);
        sq += __shfl_xor_sync(0xffffffffu, sq, off);
    }
    __shared__ float rs[8], rq[8];
    int w = tid >> 5, ln = tid & 31;
    if (ln == 0) { rs[w] = s; rq[w] = sq; }
    __syncthreads();
    s = 0.f; sq = 0.f;
    #pragma unroll
    for (int i = 0; i < 8; i++) { s += rs[i]; sq += rq[i]; }
    float mean = s * (1.f/DIMN);
    float var  = sq * (1.f/DIMN) - mean*mean;
    float rstd = rsqrtf(var + 1e-5f);
    float4 gv = reinterpret_cast<const float4*>(gamma)[tid];
    float4 bv = reinterpret_cast<const float4*>(beta)[tid];
    float4 r;
    r.x = (v.x-mean)*rstd*gv.x + bv.x;
    r.y = (v.y-mean)*rstd*gv.y + bv.y;
    r.z = (v.z-mean)*rstd*gv.z + bv.z;
    r.w = (v.w-mean)*rstd*gv.w + bv.w;
    uint32_t h0 = pack_bf16(r.x, r.y), h1 = pack_bf16(r.z, r.w);
    uint32_t l0 = pack_bf16(r.x - lofl(h0), r.y - hifl(h0));
    uint32_t l1 = pack_bf16(r.z - lofl(h1), r.w - hifl(h1));
    reinterpret_cast<uint2*>(hh + (size_t)row*512)[tid] = make_uint2(h0, h1);
    reinterpret_cast<uint2*>(hl + (size_t)row*512)[tid] = make_uint2(l0, l1);
}

// ---------------------------------------------------------------------------
// 3xBF16 GEMM on pre-split operands (NT): C = A @ B^T (+ optional Cin)
// CTA 128x128, BK=32 (16 u32 pairs), 8 warps of 64x32 tiles.
// 2-stage cp.async double buffer; inner loop = lds + mma only.
// Swizzle: phys uint4-group = c ^ ((r>>1)&3).
// ---------------------------------------------------------------------------
#define MM_SMEM 65536    // 2 stages x 4 halves x 128x16 u32

__device__ __forceinline__ void mm_prefetch(
    uint32_t sb, int stage, const uint32_t* __restrict__ Ahg,
    const uint32_t* __restrict__ Alg, const uint32_t* __restrict__ Bhg,
    const uint32_t* __restrict__ Blg, int rowBase, int colBase,
    int kb, int KPr, int tid)
{
    #pragma unroll
    for (int it = 0; it < 2; it++) {
        int l = it*256 + tid;
        int r = l >> 2, c = l & 3;
        int pg = c ^ ((r >> 1) & 3);
        uint32_t dst = sb + stage*32768 + ((r*16 + pg*4) << 2);
        size_t oa = (size_t)(rowBase + r)*KPr + kb*16 + c*4;
        size_t ob = (size_t)(colBase + r)*KPr + kb*16 + c*4;
        CP_ASYNC16(dst,         Ahg + oa);
        CP_ASYNC16(dst +  8192, Alg + oa);
        CP_ASYNC16(dst + 16384, Bhg + ob);
        CP_ASYNC16(dst + 24576, Blg + ob);
    }
}

template<bool ADD>
__global__ __launch_bounds__(256, 2)
void mm_ps(const uint32_t* __restrict__ Ahg, const uint32_t* __restrict__ Alg,
           const uint32_t* __restrict__ Bhg, const uint32_t* __restrict__ Blg,
           const float* __restrict__ Cin, float* __restrict__ C,
           int M, int N, int K)
{
    extern __shared__ uint32_t smu[];
    const uint32_t sb = smem_u32(smu);
    const int tid  = threadIdx.x;
    const int warp = tid >> 5, lane = tid & 31;
    const int g = lane >> 2, t4 = lane & 3;
    const int wm = (warp >> 2) * 64;
    const int wn = (warp & 3) * 32;
    const int rowBase = blockIdx.y * 128;
    const int colBase = blockIdx.x * 128;
    const int KPr = K >> 1;
    const int NKB = K >> 5;

    float acc[4][4][4];
    #pragma unroll
    for (int i = 0; i < 4; i++)
        #pragma unroll
        for (int j = 0; j < 4; j++)
            #pragma unroll
            for (int q = 0; q < 4; q++) acc[i][j][q] = 0.f;

    mm_prefetch(sb, 0, Ahg, Alg, Bhg, Blg, rowBase, colBase, 0, KPr, tid);
    CP_COMMIT();

    for (int kb = 0; kb < NKB; kb++) {
        if (kb + 1 < NKB) {
            mm_prefetch(sb, (kb+1)&1, Ahg, Alg, Bhg, Blg, rowBase, colBase,
                        kb+1, KPr, tid);
            CP_COMMIT();
            CP_WAIT1();
        } else {
            CP_WAIT0();
        }
        __syncthreads();

        const uint32_t* Ah = smu + (kb&1)*8192;
        const uint32_t* Al = Ah + 2048;
        const uint32_t* Bh = Al + 2048;
        const uint32_t* Bl = Bh + 2048;

        #pragma unroll
        for (int kk = 0; kk < 2; kk++) {
            uint32_t bhf[4][2], blf[4][2];
            #pragma unroll
            for (int nt = 0; nt < 4; nt++) {
                int n = wn + nt*8 + g;
                int s = (n >> 1) & 3;
                int c0 = ((2*kk)   ^ s)*4 + t4;
                int c1 = ((2*kk+1) ^ s)*4 + t4;
                bhf[nt][0] = Bh[n*16 + c0];  bhf[nt][1] = Bh[n*16 + c1];
                blf[nt][0] = Bl[n*16 + c0];  blf[nt][1] = Bl[n*16 + c1];
            }
            #pragma unroll
            for (int mt = 0; mt < 4; mt++) {
                int r1 = wm + mt*16 + g;
                int s = (r1 >> 1) & 3;
                int c0 = ((2*kk)   ^ s)*4 + t4;
                int c1 = ((2*kk+1) ^ s)*4 + t4;
                uint32_t ah[4], al[4];
                ah[0] = Ah[r1*16 + c0];  ah[1] = Ah[(r1+8)*16 + c0];
                ah[2] = Ah[r1*16 + c1];  ah[3] = Ah[(r1+8)*16 + c1];
                al[0] = Al[r1*16 + c0];  al[1] = Al[(r1+8)*16 + c0];
                al[2] = Al[r1*16 + c1];  al[3] = Al[(r1+8)*16 + c1];
                #pragma unroll
                for (int nt = 0; nt < 4; nt++) {
                    mma_bf16(acc[mt][nt], ah, bhf[nt]);
                    mma_bf16(acc[mt][nt], ah, blf[nt]);
                    mma_bf16(acc[mt][nt], al, bhf[nt]);
                }
            }
        }
        __syncthreads();
    }

    #pragma unroll
    for (int mt = 0; mt < 4; mt++) {
        int row0 = rowBase + wm + mt*16 + g;
        #pragma unroll
        for (int nt = 0; nt < 4; nt++) {
            int col = colBase + wn + nt*8 + t4*2;
            size_t o0 = (size_t)row0*N + col;
            size_t o1 = (size_t)(row0 + 8)*N + col;
            float2 v0 = make_float2(acc[mt][nt][0], acc[mt][nt][1]);
            float2 v1 = make_float2(acc[mt][nt][2], acc[mt][nt][3]);
            if (ADD) {
                float2 c0 = *reinterpret_cast<const float2*>(Cin + o0);
                float2 c1 = *reinterpret_cast<const float2*>(Cin + o1);
                v0.x += c0.x; v0.y += c0.y;
                v1.x += c1.x; v1.y += c1.y;
            }
            *reinterpret_cast<float2*>(C + o0) = v0;
            *reinterpret_cast<float2*>(C + o1) = v1;
        }
    }
}

// ---------------------------------------------------------------------------
// GEGLU: writes split packed pairs into branch hi/lo (cols 0..511 pairs)
// ---------------------------------------------------------------------------
__device__ __forceinline__ float gelu_exact(float v) {
    return 0.5f * v * (1.f + erff(v * 0.70710678118654752440f));
}
__global__ __launch_bounds__(256) void glu_kernel(
    const float* __restrict__ proj, uint32_t* __restrict__ bh,
    uint32_t* __restrict__ bl)
{
    int idx = blockIdx.x * 256 + threadIdx.x;
    int r  = idx >> 8;
    int c4 = idx & 255;
    float4 lin = *reinterpret_cast<const float4*>(&proj[(size_t)r*NPROJ + 3*DIMN + c4*4]);
    float4 pre = *reinterpret_cast<const float4*>(&proj[(size_t)r*NPROJ + 4*DIMN + c4*4]);
    float4 o;
    o.x = lin.x * gelu_exact(pre.x);
    o.y = lin.y * gelu_exact(pre.y);
    o.z = lin.z * gelu_exact(pre.z);
    o.w = lin.w * gelu_exact(pre.w);
    uint32_t h0 = pack_bf16(o.x, o.y), h1 = pack_bf16(o.z, o.w);
    uint32_t l0 = pack_bf16(o.x - lofl(h0), o.y - hifl(h0));
    uint32_t l1 = pack_bf16(o.z - lofl(h1), o.w - hifl(h1));
    *reinterpret_cast<uint2*>(&bh[(size_t)r*1024 + 2*c4]) = make_uint2(h0, h1);
    *reinterpret_cast<uint2*>(&bl[(size_t)r*1024 + 2*c4]) = make_uint2(l0, l1);
}

// ---------------------------------------------------------------------------
// Flash attention (causal, p=2 power-softmax) on 3xBF16 mma.sync.
// Unchanged from R8 except the epilogue writes split packed pairs.
// ---------------------------------------------------------------------------
#define ATV 136
#define AT_SMEM ((2*128*64 + 2*64*64 + 2*32*ATV) * 4)   // 133120 B

__global__ __launch_bounds__(256, 1) void attn_bf3(
    const float* __restrict__ proj, uint32_t* __restrict__ bhg,
    uint32_t* __restrict__ blg)
{
    extern __shared__ uint32_t su[];
    uint32_t* Qh = su;               // [128][64]
    uint32_t* Ql = Qh + 128*64;
    uint32_t* Kh = Ql + 128*64;      // [64][64]
    uint32_t* Kl = Kh + 64*64;
    uint32_t* Vh = Kl + 64*64;       // [32][ATV]
    uint32_t* Vl = Vh + 32*ATV;

    const int tid = threadIdx.x;
    const int warp = tid >> 5, lane = tid & 31;
    const int g = lane >> 2, t4 = lane & 3;
    const int wm = warp * 16;
    const int qb = (SEQL/128 - 1) - blockIdx.x;     // big tiles first
    const int bh = blockIdx.y;
    const int b = bh >> 3, h = bh & 7;
    const float scale = 0.08838834764831845f;       // 1/sqrt(128)

    const size_t rowOff = (size_t)(b * SEQL) * NPROJ;
    const int colQ = h*HDIM, colK = DIMN + h*HDIM, colV = 2*DIMN + h*HDIM;

    // ---- load + split Q [128][128]
    #pragma unroll
    for (int it = 0; it < 8; it++) {
        int linear = it*256 + tid;
        int r = linear >> 4, c = linear & 15;
        const float* src = &proj[rowOff + (size_t)(qb*128 + r)*NPROJ + colQ + c*8];
        float4 v0 = *reinterpret_cast<const float4*>(src);
        float4 v1 = *reinterpret_cast<const float4*>(src + 4);
        uint4 hh, ll; split8(v0, v1, hh, ll);
        int pg = (c ^ (r & 7)) * 4;
        *reinterpret_cast<uint4*>(Qh + r*64 + pg) = hh;
        *reinterpret_cast<uint4*>(Ql + r*64 + pg) = ll;
    }

    float m[2]  = { -INFINITY, -INFINITY };
    float S2[2] = { 0.f, 0.f };
    float O[16][4];
    #pragma unroll
    for (int i = 0; i < 16; i++)
        #pragma unroll
        for (int q = 0; q < 4; q++) O[i][q] = 0.f;

    const int qg0 = qb*128 + wm + g;
    const int KT = 2*qb + 2;

    for (int kb = 0; kb < KT; kb++) {
        __syncthreads();
        // ---- load + split K tile [64][128]
        #pragma unroll
        for (int it = 0; it < 4; it++) {
            int linear = it*256 + tid;
            int r = linear >> 4, c = linear & 15;
            const float* src = &proj[rowOff + (size_t)(kb*64 + r)*NPROJ + colK + c*8];
            float4 v0 = *reinterpret_cast<const float4*>(src);
            float4 v1 = *reinterpret_cast<const float4*>(src + 4);
            uint4 hh, ll; split8(v0, v1, hh, ll);
            int pg = (c ^ (r & 7)) * 4;
            *reinterpret_cast<uint4*>(Kh + r*64 + pg) = hh;
            *reinterpret_cast<uint4*>(Kl + r*64 + pg) = ll;
        }
        // ---- load + split V tile, packed pairs along keys
        #pragma unroll
        for (int it = 0; it < 4; it++) {
            int kp = it*8 + (tid >> 5);
            int dbase = (tid & 31) * 4;
            const float* se = &proj[rowOff + (size_t)(kb*64 + 2*kp    )*NPROJ + colV + dbase];
            const float* so = &proj[rowOff + (size_t)(kb*64 + 2*kp + 1)*NPROJ + colV + dbase];
            float4 e = *reinterpret_cast<const float4*>(se);
            float4 o = *reinterpret_cast<const float4*>(so);
            uint4 hh, ll;
            hh.x = pack_bf16(e.x, o.x); ll.x = pack_bf16(e.x - lofl(hh.x), o.x - hifl(hh.x));
            hh.y = pack_bf16(e.y, o.y); ll.y = pack_bf16(e.y - lofl(hh.y), o.y - hifl(hh.y));
            hh.z = pack_bf16(e.z, o.z); ll.z = pack_bf16(e.z - lofl(hh.z), o.z - hifl(hh.z));
            hh.w = pack_bf16(e.w, o.w); ll.w = pack_bf16(e.w - lofl(hh.w), o.w - hifl(hh.w));
            *reinterpret_cast<uint4*>(Vh + kp*ATV + dbase) = hh;
            *reinterpret_cast<uint4*>(Vl + kp*ATV + dbase) = ll;
        }
        __syncthreads();

        if (kb*64 > qb*128 + wm + 15) continue;     // tile fully masked for warp

        // ---- S = Q K^T
        float s[8][4];
        #pragma unroll
        for (int nt = 0; nt < 8; nt++)
            #pragma unroll
            for (int q = 0; q < 4; q++) s[nt][q] = 0.f;
        #pragma unroll 2
        for (int kk = 0; kk < 8; kk++) {
            int c0 = ((2*kk)   ^ g)*4 + t4;
            int c1 = ((2*kk+1) ^ g)*4 + t4;
            uint32_t ah[4], al[4];
            ah[0] = Qh[(wm+g  )*64 + c0];  ah[1] = Qh[(wm+8+g)*64 + c0];
            ah[2] = Qh[(wm+g  )*64 + c1];  ah[3] = Qh[(wm+8+g)*64 + c1];
            al[0] = Ql[(wm+g  )*64 + c0];  al[1] = Ql[(wm+8+g)*64 + c0];
            al[2] = Ql[(wm+g  )*64 + c1];  al[3] = Ql[(wm+8+g)*64 + c1];
            #pragma unroll
            for (int nt = 0; nt < 8; nt++) {
                int n = nt*8 + g;
                uint32_t bh2[2] = { Kh[n*64 + c0], Kh[n*64 + c1] };
                uint32_t bl2[2] = { Kl[n*64 + c0], Kl[n*64 + c1] };
                mma_bf16(s[nt], ah, bh2);
                mma_bf16(s[nt], ah, bl2);
                mma_bf16(s[nt], al, bh2);
            }
        }

        // ---- scale + causal mask + warp-local row max
        float lmax[2] = { -INFINITY, -INFINITY };
        const bool need_mask = (kb*64 + 63 > qb*128 + wm);
        #pragma unroll
        for (int nt = 0; nt < 8; nt++)
            #pragma unroll
            for (int q = 0; q < 4; q++) {
                int ri = q >> 1;
                float v = s[nt][q] * scale;
                if (need_mask) {
                    int kg = kb*64 + nt*8 + 2*t4 + (q & 1);
                    if (kg > qg0 + 8*ri) v = -INFINITY;
                }
                s[nt][q] = v;
                lmax[ri] = fmaxf(lmax[ri], v);
            }
        #pragma unroll
        for (int off = 1; off < 4; off <<= 1) {
            lmax[0] = fmaxf(lmax[0], __shfl_xor_sync(0xffffffffu, lmax[0], off));
            lmax[1] = fmaxf(lmax[1], __shfl_xor_sync(0xffffffffu, lmax[1], off));
        }

        // ---- online p=2 softmax update
        float mn[2], corr[2], lsum[2];
        #pragma unroll
        for (int ri = 0; ri < 2; ri++) {
            mn[ri]   = fmaxf(m[ri], lmax[ri]);
            corr[ri] = __expf(m[ri] - mn[ri]);
            m[ri]    = mn[ri];
            lsum[ri] = 0.f;
        }
        #pragma unroll
        for (int nt = 0; nt < 8; nt++)
            #pragma unroll
            for (int q = 0; q < 4; q++) {
                int ri = q >> 1;
                float p = __expf(s[nt][q] - mn[ri]);
                s[nt][q] = p;
                lsum[ri] += p * p;
            }
        #pragma unroll
        for (int off = 1; off < 4; off <<= 1) {
            lsum[0] += __shfl_xor_sync(0xffffffffu, lsum[0], off);
            lsum[1] += __shfl_xor_sync(0xffffffffu, lsum[1], off);
        }
        #pragma unroll
        for (int ri = 0; ri < 2; ri++)
            S2[ri] = S2[ri]*corr[ri]*corr[ri] + lsum[ri];
        #pragma unroll
        for (int nt = 0; nt < 16; nt++)
            #pragma unroll
            for (int q = 0; q < 4; q++) O[nt][q] *= corr[q >> 1];

        // ---- O += P V
        #pragma unroll
        for (int kk = 0; kk < 4; kk++) {
            uint32_t ph[4], pl[4];
            ph[0] = pack_bf16(s[2*kk][0],   s[2*kk][1]);
            ph[1] = pack_bf16(s[2*kk][2],   s[2*kk][3]);
            ph[2] = pack_bf16(s[2*kk+1][0], s[2*kk+1][1]);
            ph[3] = pack_bf16(s[2*kk+1][2], s[2*kk+1][3]);
            pl[0] = pack_bf16(s[2*kk][0]   - lofl(ph[0]), s[2*kk][1]   - hifl(ph[0]));
            pl[1] = pack_bf16(s[2*kk][2]   - lofl(ph[1]), s[2*kk][3]   - hifl(ph[1]));
            pl[2] = pack_bf16(s[2*kk+1][0] - lofl(ph[2]), s[2*kk+1][1] - hifl(ph[2]));
            pl[3] = pack_bf16(s[2*kk+1][2] - lofl(ph[3]), s[2*kk+1][3] - hifl(ph[3]));
            int vr0 = (kk*8 + t4)*ATV;
            int vr1 = (kk*8 + 4 + t4)*ATV;
            #pragma unroll
            for (int nt = 0; nt < 16; nt++) {
                int n = nt*8 + g;
                uint32_t vbh[2] = { Vh[vr0 + n], Vh[vr1 + n] };
                uint32_t vbl[2] = { Vl[vr0 + n], Vl[vr1 + n] };
                mma_bf16(O[nt], ph, vbh);
                mma_bf16(O[nt], ph, vbl);
                mma_bf16(O[nt], pl, vbh);
            }
        }
    }

    // ---- epilogue: scale by rsqrt(S2), split-pack, store to branch hi/lo
    float inv0 = rsqrtf(S2[0]);
    float inv1 = rsqrtf(S2[1]);
    const size_t rg0 = (size_t)(b*SEQL + qb*128 + wm + g);
    const size_t rg1 = rg0 + 8;
    const int cp0 = 512 + h*64 + t4;
    #pragma unroll
    for (int nt = 0; nt < 16; nt++) {
        float a0 = O[nt][0]*inv0, a1 = O[nt][1]*inv0;
        uint32_t p0 = pack_bf16(a0, a1);
        uint32_t q0 = pack_bf16(a0 - lofl(p0), a1 - hifl(p0));
        bhg[rg0*1024 + cp0 + nt*4] = p0;
        blg[rg0*1024 + cp0 + nt*4] = q0;
        float b0 = O[nt][2]*inv1, b1 = O[nt][3]*inv1;
        uint32_t p1 = pack_bf16(b0, b1);
        uint32_t q1 = pack_bf16(b0 - lofl(p1), b1 - hifl(p1));
        bhg[rg1*1024 + cp0 + nt*4] = p1;
        blg[rg1*1024 + cp0 + nt*4] = q1;
    }
}

// ---------------------------------------------------------------------------
// Launch
// ---------------------------------------------------------------------------
extern "C" void kernel_launch(void* const* d_in, const int* in_sizes, int n_in,
                              void* d_out, int out_size)
{
    const float* x     = (const float*)d_in[0];
    const float* gamma = (const float*)d_in[1];
    const float* beta  = (const float*)d_in[2];
    const float* w_qkv = (const float*)d_in[3];
    const float* w_out = (const float*)d_in[4];
    float* out = (float*)d_out;

    uint32_t *hh, *hl, *wqh, *wql, *woh, *wol, *bh, *bl;
    float *projbuf;
    cudaGetSymbolAddress((void**)&hh,  g_hh);
    cudaGetSymbolAddress((void**)&hl,  g_hl);
    cudaGetSymbolAddress((void**)&wqh, g_wqh);
    cudaGetSymbolAddress((void**)&wql, g_wql);
    cudaGetSymbolAddress((void**)&woh, g_woh);
    cudaGetSymbolAddress((void**)&wol, g_wol);
    cudaGetSymbolAddress((void**)&bh,  g_bh);
    cudaGetSymbolAddress((void**)&bl,  g_bl);
    cudaGetSymbolAddress((void**)&projbuf, g_proj);

    cudaFuncSetAttribute(attn_bf3, cudaFuncAttributeMaxDynamicSharedMemorySize, AT_SMEM);
    cudaFuncSetAttribute(mm_ps<false>, cudaFuncAttributeMaxDynamicSharedMemorySize, MM_SMEM);
    cudaFuncSetAttribute(mm_ps<true>,  cudaFuncAttributeMaxDynamicSharedMemorySize, MM_SMEM);

    // 0) pre-split weights
    wsplit_kernel<<<(NPROJ*DIMN/4)/256, 256>>>(w_qkv, wqh, wql);
    wsplit_kernel<<<(DIMN*NBR/4)/256, 256>>>(w_out, woh, wol);

    // 1) LayerNorm (writes split h)
    ln_kernel<<<NROWS, 256>>>(x, gamma, beta, hh, hl);

    // 2) proj = h @ w_qkv^T   [8192 x 5120], K=1024
    {
        dim3 grid(NPROJ/128, NROWS/128);
        mm_ps<false><<<grid, 256, MM_SMEM>>>(hh, hl, wqh, wql, nullptr, projbuf,
                                             NROWS, NPROJ, DIMN);
    }

    // 3) GEGLU half of branch (split write)
    glu_kernel<<<(NROWS*DIMN)/4/256, 256>>>(projbuf, bh, bl);

    // 4) Attention half of branch (split write)
    {
        dim3 grid(SEQL/128, BATCH*NHEADS);
        attn_bf3<<<grid, 256, AT_SMEM>>>(projbuf, bh, bl);
    }

    // 5) out = x + branch @ w_out^T   [8192 x 1024], K=2048
    {
        dim3 grid(DIMN/128, NROWS/128);
        mm_ps<true><<<grid, 256, MM_SMEM>>>(bh, bl, woh, wol, x, out,
                                            NROWS, DIMN, NBR);
    }
}

// round 15
// speedup vs baseline: 3.8357x; 1.0331x over previous
#include <cuda_runtime.h>
#include <math.h>
#include <stdint.h>

// Problem constants
#define DIMN 1024
#define SEQL 2048
#define BATCH 4
#define NHEADS 8
#define HDIM 128
#define NROWS (BATCH*SEQL)   // 8192
#define NPROJ (5*DIMN)       // 5120
#define NBR (2*DIMN)         // 2048

// Scratch (static __device__ arrays -- allocation-free per harness rules)
// Packed bf16-pair hi/lo arrays: X[r][k/2] u32, lo16=even k, hi16=odd k.
__device__ uint32_t g_hh[(size_t)NROWS*512],  g_hl[(size_t)NROWS*512];   // LN(x)
__device__ uint32_t g_wqh[(size_t)NPROJ*512], g_wql[(size_t)NPROJ*512];  // w_qkv
__device__ uint32_t g_woh[(size_t)DIMN*1024], g_wol[(size_t)DIMN*1024]; // w_out
__device__ uint32_t g_bh[(size_t)NROWS*1024], g_bl[(size_t)NROWS*1024]; // branch
__device__ float    g_proj[(size_t)NROWS*NPROJ];                        // f32 proj

// ===========================================================================
// bf16 helpers (3xBF16 split: D += AhBh + AhBl + AlBh)
// ===========================================================================
__device__ __forceinline__ uint32_t pack_bf16(float e, float o) {
    uint32_t r;
    asm("cvt.rn.bf16x2.f32 %0, %1, %2;" : "=r"(r) : "f"(o), "f"(e));
    return r;
}
__device__ __forceinline__ float lofl(uint32_t p){ return __uint_as_float(p << 16); }
__device__ __forceinline__ float hifl(uint32_t p){ return __uint_as_float(p & 0xFFFF0000u); }

__device__ __forceinline__ void split8(float4 v0, float4 v1, uint4& h, uint4& l) {
    h.x = pack_bf16(v0.x, v0.y);
    h.y = pack_bf16(v0.z, v0.w);
    h.z = pack_bf16(v1.x, v1.y);
    h.w = pack_bf16(v1.z, v1.w);
    l.x = pack_bf16(v0.x - lofl(h.x), v0.y - hifl(h.x));
    l.y = pack_bf16(v0.z - lofl(h.y), v0.w - hifl(h.y));
    l.z = pack_bf16(v1.x - lofl(h.z), v1.y - hifl(h.z));
    l.w = pack_bf16(v1.z - lofl(h.w), v1.w - hifl(h.w));
}

__device__ __forceinline__ void mma_bf16(float* c, const uint32_t* a,
                                         const uint32_t* b) {
    asm volatile(
        "mma.sync.aligned.m16n8k16.row.col.f32.bf16.bf16.f32 "
        "{%0,%1,%2,%3}, {%4,%5,%6,%7}, {%8,%9}, {%0,%1,%2,%3};"
        : "+f"(c[0]), "+f"(c[1]), "+f"(c[2]), "+f"(c[3])
        : "r"(a[0]), "r"(a[1]), "r"(a[2]), "r"(a[3]), "r"(b[0]), "r"(b[1]));
}

__device__ __forceinline__ void ldsm4(uint32_t& r0, uint32_t& r1, uint32_t& r2,
                                      uint32_t& r3, uint32_t addr) {
    asm volatile("ldmatrix.sync.aligned.m8n8.x4.shared.b16 {%0,%1,%2,%3}, [%4];"
                 : "=r"(r0), "=r"(r1), "=r"(r2), "=r"(r3) : "r"(addr));
}

__device__ __forceinline__ uint32_t smem_u32(const void* p) {
    uint32_t a;
    asm("{ .reg .u64 t; cvta.to.shared.u64 t, %1; cvt.u32.u64 %0, t; }"
        : "=r"(a) : "l"(p));
    return a;
}
#define CP_ASYNC16(dst, src) \
    asm volatile("cp.async.ca.shared.global [%0], [%1], 16;" \
                 :: "r"(dst), "l"(src) : "memory")
#define CP_COMMIT() asm volatile("cp.async.commit_group;" ::: "memory")

// ---------------------------------------------------------------------------
// Weight split: W[R][K] f32 -> packed pair hi/lo u32 [R][K/2]
// ---------------------------------------------------------------------------
__global__ __launch_bounds__(256) void wsplit_kernel(
    const float* __restrict__ W, uint32_t* __restrict__ Wh,
    uint32_t* __restrict__ Wl)
{
    int idx = blockIdx.x*256 + threadIdx.x;
    float4 v = reinterpret_cast<const float4*>(W)[idx];
    uint32_t h0 = pack_bf16(v.x, v.y), h1 = pack_bf16(v.z, v.w);
    uint32_t l0 = pack_bf16(v.x - lofl(h0), v.y - hifl(h0));
    uint32_t l1 = pack_bf16(v.z - lofl(h1), v.w - hifl(h1));
    reinterpret_cast<uint2*>(Wh)[idx] = make_uint2(h0, h1);
    reinterpret_cast<uint2*>(Wl)[idx] = make_uint2(l0, l1);
}

// ---------------------------------------------------------------------------
// LayerNorm: one block per row of 1024; writes split packed pairs directly.
// ---------------------------------------------------------------------------
__global__ __launch_bounds__(256) void ln_kernel(
    const float* __restrict__ x, const float* __restrict__ gamma,
    const float* __restrict__ beta, uint32_t* __restrict__ hh,
    uint32_t* __restrict__ hl)
{
    int row = blockIdx.x, tid = threadIdx.x;
    const float4 v = reinterpret_cast<const float4*>(x + (size_t)row*DIMN)[tid];
    float s  = v.x + v.y + v.z + v.w;
    float sq = v.x*v.x + v.y*v.y + v.z*v.z + v.w*v.w;
    #pragma unroll
    for (int off = 16; off; off >>= 1) {
        s  += __shfl_xor_sync(0xffffffffu, s,  off);
        sq += __shfl_xor_sync(0xffffffffu, sq, off);
    }
    __shared__ float rs[8], rq[8];
    int w = tid >> 5, ln = tid & 31;
    if (ln == 0) { rs[w] = s; rq[w] = sq; }
    __syncthreads();
    s = 0.f; sq = 0.f;
    #pragma unroll
    for (int i = 0; i < 8; i++) { s += rs[i]; sq += rq[i]; }
    float mean = s * (1.f/DIMN);
    float var  = sq * (1.f/DIMN) - mean*mean;
    float rstd = rsqrtf(var + 1e-5f);
    float4 gv = reinterpret_cast<const float4*>(gamma)[tid];
    float4 bv = reinterpret_cast<const float4*>(beta)[tid];
    float4 r;
    r.x = (v.x-mean)*rstd*gv.x + bv.x;
    r.y = (v.y-mean)*rstd*gv.y + bv.y;
    r.z = (v.z-mean)*rstd*gv.z + bv.z;
    r.w = (v.w-mean)*rstd*gv.w + bv.w;
    uint32_t h0 = pack_bf16(r.x, r.y), h1 = pack_bf16(r.z, r.w);
    uint32_t l0 = pack_bf16(r.x - lofl(h0), r.y - hifl(h0));
    uint32_t l1 = pack_bf16(r.z - lofl(h1), r.w - hifl(h1));
    reinterpret_cast<uint2*>(hh + (size_t)row*512)[tid] = make_uint2(h0, h1);
    reinterpret_cast<uint2*>(hl + (size_t)row*512)[tid] = make_uint2(l0, l1);
}

// ---------------------------------------------------------------------------
// 3xBF16 GEMM (NT), pre-split operands: C = A @ B^T (+ optional Cin)
// CTA 128x128, BK=32 (16 u32 pairs), 8 warps (4x2) of 32x64 tiles.
// 3-stage cp.async ring (98 KB, 2 CTAs/SM), ONE __syncthreads per k-block,
// ldmatrix.x4 fragment loads.
// Smem swizzle: phys uint4-group = c ^ ((r>>1)&3)  (conflict-free LDSM).
// ---------------------------------------------------------------------------
#define NST 3
#define STAGE_BYTES ((128 + 128)*128)          // 32768
#define MM_SMEM (NST*STAGE_BYTES)              // 98304
#define OFF_AL (128*64)                        // bytes: Al after Ah
#define OFF_BH (2*128*64)                      // bytes: Bh after Al

template<bool ADD>
__global__ __launch_bounds__(256, 2)
void mm_ps(const uint32_t* __restrict__ Ahg, const uint32_t* __restrict__ Alg,
           const uint32_t* __restrict__ Bhg, const uint32_t* __restrict__ Blg,
           const float* __restrict__ Cin, float* __restrict__ C,
           int M, int N, int K)
{
    extern __shared__ uint32_t smu[];
    const uint32_t sb = smem_u32(smu);
    const int tid = threadIdx.x;
    const int warp = tid >> 5, lane = tid & 31;
    const int g = lane >> 2, t4 = lane & 3;
    const int wm = (warp >> 1) * 32;
    const int wn = (warp & 1) * 64;
    const int rowBase = blockIdx.y * 128;
    const int colBase = blockIdx.x * 128;
    const int KPr = K >> 1;
    const int NKB = K >> 5;

    auto pref = [&](int st, int kb) {
        uint32_t stBase = sb + st*STAGE_BYTES;
        #pragma unroll
        for (int it = 0; it < 4; it++) {
            int idx = it*256 + tid;
            bool isB = (idx >= 512);
            int li = isB ? idx - 512 : idx;
            int r = li >> 2, c = li & 3;
            int pg = c ^ ((r >> 1) & 3);
            uint32_t d = stBase + (isB ? OFF_BH : 0) + r*64 + pg*16;
            size_t so = (size_t)((isB ? colBase : rowBase) + r)*KPr + kb*16 + c*4;
            CP_ASYNC16(d, (isB ? Bhg : Ahg) + so);
            CP_ASYNC16(d + 8192, (isB ? Blg : Alg) + so);
        }
    };

    // ldmatrix per-lane address precompute
    const int mid = lane >> 3, lr = lane & 7;
    const int agsel = mid >> 1;               // A k-group select
    const int bgsel = mid & 1;                // B k-group select
    int aRowOff[2], aSw[2];
    #pragma unroll
    for (int mt = 0; mt < 2; mt++) {
        int row = wm + mt*16 + (mid & 1)*8 + lr;
        aRowOff[mt] = row*64;
        aSw[mt] = (row >> 1) & 3;
    }
    int bRowOff[4], bSw[4];
    #pragma unroll
    for (int p = 0; p < 4; p++) {
        int n = wn + p*16 + (mid >> 1)*8 + lr;
        bRowOff[p] = n*64;
        bSw[p] = (n >> 1) & 3;
    }

    float acc[2][8][4];
    #pragma unroll
    for (int i = 0; i < 2; i++)
        #pragma unroll
        for (int j = 0; j < 8; j++)
            #pragma unroll
            for (int q = 0; q < 4; q++) acc[i][j][q] = 0.f;

    #pragma unroll
    for (int i = 0; i < NST-1; i++) { pref(i, i); CP_COMMIT(); }

    int stC = 0, stP = NST-1;
    for (int kb = 0; kb < NKB; kb++) {
        asm volatile("cp.async.wait_group %0;" :: "n"(NST-2) : "memory");
        __syncthreads();
        if (kb + NST-1 < NKB) pref(stP, kb + NST-1);
        CP_COMMIT();                  // dummy commit at tail keeps counts uniform

        const uint32_t stBase = sb + stC*STAGE_BYTES;
        #pragma unroll
        for (int kk = 0; kk < 2; kk++) {
            uint32_t ah[2][4], al[2][4];
            #pragma unroll
            for (int mt = 0; mt < 2; mt++) {
                uint32_t ao = stBase + aRowOff[mt] + (((2*kk + agsel) ^ aSw[mt]) << 4);
                ldsm4(ah[mt][0], ah[mt][1], ah[mt][2], ah[mt][3], ao);
                ldsm4(al[mt][0], al[mt][1], al[mt][2], al[mt][3], ao + OFF_AL);
            }
            #pragma unroll
            for (int p = 0; p < 4; p++) {
                uint32_t bo = stBase + OFF_BH + bRowOff[p]
                            + (((2*kk + bgsel) ^ bSw[p]) << 4);
                uint32_t bh4[4], bl4[4];
                ldsm4(bh4[0], bh4[1], bh4[2], bh4[3], bo);
                ldsm4(bl4[0], bl4[1], bl4[2], bl4[3], bo + 8192);
                #pragma unroll
                for (int mt = 0; mt < 2; mt++) {
                    mma_bf16(acc[mt][2*p],   ah[mt], bh4);
                    mma_bf16(acc[mt][2*p],   ah[mt], bl4);
                    mma_bf16(acc[mt][2*p],   al[mt], bh4);
                    mma_bf16(acc[mt][2*p+1], ah[mt], bh4 + 2);
                    mma_bf16(acc[mt][2*p+1], ah[mt], bl4 + 2);
                    mma_bf16(acc[mt][2*p+1], al[mt], bh4 + 2);
                }
            }
        }
        stC = (stC+1 == NST) ? 0 : stC+1;
        stP = (stP+1 == NST) ? 0 : stP+1;
    }

    // epilogue
    #pragma unroll
    for (int mt = 0; mt < 2; mt++) {
        int row0 = rowBase + wm + mt*16 + g;
        #pragma unroll
        for (int nt = 0; nt < 8; nt++) {
            int col = colBase + wn + nt*8 + t4*2;
            size_t o0 = (size_t)row0*N + col;
            size_t o1 = o0 + (size_t)8*N;
            float2 v0 = make_float2(acc[mt][nt][0], acc[mt][nt][1]);
            float2 v1 = make_float2(acc[mt][nt][2], acc[mt][nt][3]);
            if (ADD) {
                float2 c0 = *reinterpret_cast<const float2*>(Cin + o0);
                float2 c1 = *reinterpret_cast<const float2*>(Cin + o1);
                v0.x += c0.x; v0.y += c0.y;
                v1.x += c1.x; v1.y += c1.y;
            }
            *reinterpret_cast<float2*>(C + o0) = v0;
            *reinterpret_cast<float2*>(C + o1) = v1;
        }
    }
}

// ---------------------------------------------------------------------------
// GEGLU: writes split packed pairs into branch hi/lo (cols 0..511 pairs)
// ---------------------------------------------------------------------------
__device__ __forceinline__ float gelu_exact(float v) {
    return 0.5f * v * (1.f + erff(v * 0.70710678118654752440f));
}
__global__ __launch_bounds__(256) void glu_kernel(
    const float* __restrict__ proj, uint32_t* __restrict__ bh,
    uint32_t* __restrict__ bl)
{
    int idx = blockIdx.x * 256 + threadIdx.x;
    int r  = idx >> 8;
    int c4 = idx & 255;
    float4 lin = *reinterpret_cast<const float4*>(&proj[(size_t)r*NPROJ + 3*DIMN + c4*4]);
    float4 pre = *reinterpret_cast<const float4*>(&proj[(size_t)r*NPROJ + 4*DIMN + c4*4]);
    float4 o;
    o.x = lin.x * gelu_exact(pre.x);
    o.y = lin.y * gelu_exact(pre.y);
    o.z = lin.z * gelu_exact(pre.z);
    o.w = lin.w * gelu_exact(pre.w);
    uint32_t h0 = pack_bf16(o.x, o.y), h1 = pack_bf16(o.z, o.w);
    uint32_t l0 = pack_bf16(o.x - lofl(h0), o.y - hifl(h0));
    uint32_t l1 = pack_bf16(o.z - lofl(h1), o.w - hifl(h1));
    *reinterpret_cast<uint2*>(&bh[(size_t)r*1024 + 2*c4]) = make_uint2(h0, h1);
    *reinterpret_cast<uint2*>(&bl[(size_t)r*1024 + 2*c4]) = make_uint2(l0, l1);
}

// ---------------------------------------------------------------------------
// Flash attention (causal, p=2 power-softmax) on 3xBF16 mma.sync.
// Unchanged from R10 (passing).
// ---------------------------------------------------------------------------
#define ATV 136
#define AT_SMEM ((2*128*64 + 2*64*64 + 2*32*ATV) * 4)   // 133120 B

__global__ __launch_bounds__(256, 1) void attn_bf3(
    const float* __restrict__ proj, uint32_t* __restrict__ bhg,
    uint32_t* __restrict__ blg)
{
    extern __shared__ uint32_t su[];
    uint32_t* Qh = su;               // [128][64]
    uint32_t* Ql = Qh + 128*64;
    uint32_t* Kh = Ql + 128*64;      // [64][64]
    uint32_t* Kl = Kh + 64*64;
    uint32_t* Vh = Kl + 64*64;       // [32][ATV]
    uint32_t* Vl = Vh + 32*ATV;

    const int tid = threadIdx.x;
    const int warp = tid >> 5, lane = tid & 31;
    const int g = lane >> 2, t4 = lane & 3;
    const int wm = warp * 16;
    const int qb = (SEQL/128 - 1) - blockIdx.x;     // big tiles first
    const int bh = blockIdx.y;
    const int b = bh >> 3, h = bh & 7;
    const float scale = 0.08838834764831845f;       // 1/sqrt(128)

    const size_t rowOff = (size_t)(b * SEQL) * NPROJ;
    const int colQ = h*HDIM, colK = DIMN + h*HDIM, colV = 2*DIMN + h*HDIM;

    // ---- load + split Q [128][128]
    #pragma unroll
    for (int it = 0; it < 8; it++) {
        int linear = it*256 + tid;
        int r = linear >> 4, c = linear & 15;
        const float* src = &proj[rowOff + (size_t)(qb*128 + r)*NPROJ + colQ + c*8];
        float4 v0 = *reinterpret_cast<const float4*>(src);
        float4 v1 = *reinterpret_cast<const float4*>(src + 4);
        uint4 hh, ll; split8(v0, v1, hh, ll);
        int pg = (c ^ (r & 7)) * 4;
        *reinterpret_cast<uint4*>(Qh + r*64 + pg) = hh;
        *reinterpret_cast<uint4*>(Ql + r*64 + pg) = ll;
    }

    float m[2]  = { -INFINITY, -INFINITY };
    float S2[2] = { 0.f, 0.f };
    float O[16][4];
    #pragma unroll
    for (int i = 0; i < 16; i++)
        #pragma unroll
        for (int q = 0; q < 4; q++) O[i][q] = 0.f;

    const int qg0 = qb*128 + wm + g;
    const int KT = 2*qb + 2;

    for (int kb = 0; kb < KT; kb++) {
        __syncthreads();
        // ---- load + split K tile [64][128]
        #pragma unroll
        for (int it = 0; it < 4; it++) {
            int linear = it*256 + tid;
            int r = linear >> 4, c = linear & 15;
            const float* src = &proj[rowOff + (size_t)(kb*64 + r)*NPROJ + colK + c*8];
            float4 v0 = *reinterpret_cast<const float4*>(src);
            float4 v1 = *reinterpret_cast<const float4*>(src + 4);
            uint4 hh, ll; split8(v0, v1, hh, ll);
            int pg = (c ^ (r & 7)) * 4;
            *reinterpret_cast<uint4*>(Kh + r*64 + pg) = hh;
            *reinterpret_cast<uint4*>(Kl + r*64 + pg) = ll;
        }
        // ---- load + split V tile, packed pairs along keys
        #pragma unroll
        for (int it = 0; it < 4; it++) {
            int kp = it*8 + (tid >> 5);
            int dbase = (tid & 31) * 4;
            const float* se = &proj[rowOff + (size_t)(kb*64 + 2*kp    )*NPROJ + colV + dbase];
            const float* so = &proj[rowOff + (size_t)(kb*64 + 2*kp + 1)*NPROJ + colV + dbase];
            float4 e = *reinterpret_cast<const float4*>(se);
            float4 o = *reinterpret_cast<const float4*>(so);
            uint4 hh, ll;
            hh.x = pack_bf16(e.x, o.x); ll.x = pack_bf16(e.x - lofl(hh.x), o.x - hifl(hh.x));
            hh.y = pack_bf16(e.y, o.y); ll.y = pack_bf16(e.y - lofl(hh.y), o.y - hifl(hh.y));
            hh.z = pack_bf16(e.z, o.z); ll.z = pack_bf16(e.z - lofl(hh.z), o.z - hifl(hh.z));
            hh.w = pack_bf16(e.w, o.w); ll.w = pack_bf16(e.w - lofl(hh.w), o.w - hifl(hh.w));
            *reinterpret_cast<uint4*>(Vh + kp*ATV + dbase) = hh;
            *reinterpret_cast<uint4*>(Vl + kp*ATV + dbase) = ll;
        }
        __syncthreads();

        if (kb*64 > qb*128 + wm + 15) continue;     // tile fully masked for warp

        // ---- S = Q K^T
        float s[8][4];
        #pragma unroll
        for (int nt = 0; nt < 8; nt++)
            #pragma unroll
            for (int q = 0; q < 4; q++) s[nt][q] = 0.f;
        #pragma unroll 2
        for (int kk = 0; kk < 8; kk++) {
            int c0 = ((2*kk)   ^ g)*4 + t4;
            int c1 = ((2*kk+1) ^ g)*4 + t4;
            uint32_t ah[4], al[4];
            ah[0] = Qh[(wm+g  )*64 + c0];  ah[1] = Qh[(wm+8+g)*64 + c0];
            ah[2] = Qh[(wm+g  )*64 + c1];  ah[3] = Qh[(wm+8+g)*64 + c1];
            al[0] = Ql[(wm+g  )*64 + c0];  al[1] = Ql[(wm+8+g)*64 + c0];
            al[2] = Ql[(wm+g  )*64 + c1];  al[3] = Ql[(wm+8+g)*64 + c1];
            #pragma unroll
            for (int nt = 0; nt < 8; nt++) {
                int n = nt*8 + g;
                uint32_t bh2[2] = { Kh[n*64 + c0], Kh[n*64 + c1] };
                uint32_t bl2[2] = { Kl[n*64 + c0], Kl[n*64 + c1] };
                mma_bf16(s[nt], ah, bh2);
                mma_bf16(s[nt], ah, bl2);
                mma_bf16(s[nt], al, bh2);
            }
        }

        // ---- scale + causal mask + warp-local row max
        float lmax[2] = { -INFINITY, -INFINITY };
        const bool need_mask = (kb*64 + 63 > qb*128 + wm);
        #pragma unroll
        for (int nt = 0; nt < 8; nt++)
            #pragma unroll
            for (int q = 0; q < 4; q++) {
                int ri = q >> 1;
                float v = s[nt][q] * scale;
                if (need_mask) {
                    int kg = kb*64 + nt*8 + 2*t4 + (q & 1);
                    if (kg > qg0 + 8*ri) v = -INFINITY;
                }
                s[nt][q] = v;
                lmax[ri] = fmaxf(lmax[ri], v);
            }
        #pragma unroll
        for (int off = 1; off < 4; off <<= 1) {
            lmax[0] = fmaxf(lmax[0], __shfl_xor_sync(0xffffffffu, lmax[0], off));
            lmax[1] = fmaxf(lmax[1], __shfl_xor_sync(0xffffffffu, lmax[1], off));
        }

        // ---- online p=2 softmax update
        float mn[2], corr[2], lsum[2];
        #pragma unroll
        for (int ri = 0; ri < 2; ri++) {
            mn[ri]   = fmaxf(m[ri], lmax[ri]);
            corr[ri] = __expf(m[ri] - mn[ri]);
            m[ri]    = mn[ri];
            lsum[ri] = 0.f;
        }
        #pragma unroll
        for (int nt = 0; nt < 8; nt++)
            #pragma unroll
            for (int q = 0; q < 4; q++) {
                int ri = q >> 1;
                float p = __expf(s[nt][q] - mn[ri]);
                s[nt][q] = p;
                lsum[ri] += p * p;
            }
        #pragma unroll
        for (int off = 1; off < 4; off <<= 1) {
            lsum[0] += __shfl_xor_sync(0xffffffffu, lsum[0], off);
            lsum[1] += __shfl_xor_sync(0xffffffffu, lsum[1], off);
        }
        #pragma unroll
        for (int ri = 0; ri < 2; ri++)
            S2[ri] = S2[ri]*corr[ri]*corr[ri] + lsum[ri];
        #pragma unroll
        for (int nt = 0; nt < 16; nt++)
            #pragma unroll
            for (int q = 0; q < 4; q++) O[nt][q] *= corr[q >> 1];

        // ---- O += P V
        #pragma unroll
        for (int kk = 0; kk < 4; kk++) {
            uint32_t ph[4], pl[4];
            ph[0] = pack_bf16(s[2*kk][0],   s[2*kk][1]);
            ph[1] = pack_bf16(s[2*kk][2],   s[2*kk][3]);
            ph[2] = pack_bf16(s[2*kk+1][0], s[2*kk+1][1]);
            ph[3] = pack_bf16(s[2*kk+1][2], s[2*kk+1][3]);
            pl[0] = pack_bf16(s[2*kk][0]   - lofl(ph[0]), s[2*kk][1]   - hifl(ph[0]));
            pl[1] = pack_bf16(s[2*kk][2]   - lofl(ph[1]), s[2*kk][3]   - hifl(ph[1]));
            pl[2] = pack_bf16(s[2*kk+1][0] - lofl(ph[2]), s[2*kk+1][1] - hifl(ph[2]));
            pl[3] = pack_bf16(s[2*kk+1][2] - lofl(ph[3]), s[2*kk+1][3] - hifl(ph[3]));
            int vr0 = (kk*8 + t4)*ATV;
            int vr1 = (kk*8 + 4 + t4)*ATV;
            #pragma unroll
            for (int nt = 0; nt < 16; nt++) {
                int n = nt*8 + g;
                uint32_t vbh[2] = { Vh[vr0 + n], Vh[vr1 + n] };
                uint32_t vbl[2] = { Vl[vr0 + n], Vl[vr1 + n] };
                mma_bf16(O[nt], ph, vbh);
                mma_bf16(O[nt], ph, vbl);
                mma_bf16(O[nt], pl, vbh);
            }
        }
    }

    // ---- epilogue: scale by rsqrt(S2), split-pack, store to branch hi/lo
    float inv0 = rsqrtf(S2[0]);
    float inv1 = rsqrtf(S2[1]);
    const size_t rg0 = (size_t)(b*SEQL + qb*128 + wm + g);
    const size_t rg1 = rg0 + 8;
    const int cp0 = 512 + h*64 + t4;
    #pragma unroll
    for (int nt = 0; nt < 16; nt++) {
        float a0 = O[nt][0]*inv0, a1 = O[nt][1]*inv0;
        uint32_t p0 = pack_bf16(a0, a1);
        uint32_t q0 = pack_bf16(a0 - lofl(p0), a1 - hifl(p0));
        bhg[rg0*1024 + cp0 + nt*4] = p0;
        blg[rg0*1024 + cp0 + nt*4] = q0;
        float b0 = O[nt][2]*inv1, b1 = O[nt][3]*inv1;
        uint32_t p1 = pack_bf16(b0, b1);
        uint32_t q1 = pack_bf16(b0 - lofl(p1), b1 - hifl(p1));
        bhg[rg1*1024 + cp0 + nt*4] = p1;
        blg[rg1*1024 + cp0 + nt*4] = q1;
    }
}

// ---------------------------------------------------------------------------
// Launch
// ---------------------------------------------------------------------------
extern "C" void kernel_launch(void* const* d_in, const int* in_sizes, int n_in,
                              void* d_out, int out_size)
{
    const float* x     = (const float*)d_in[0];
    const float* gamma = (const float*)d_in[1];
    const float* beta  = (const float*)d_in[2];
    const float* w_qkv = (const float*)d_in[3];
    const float* w_out = (const float*)d_in[4];
    float* out = (float*)d_out;

    uint32_t *hh, *hl, *wqh, *wql, *woh, *wol, *bh, *bl;
    float *projbuf;
    cudaGetSymbolAddress((void**)&hh,  g_hh);
    cudaGetSymbolAddress((void**)&hl,  g_hl);
    cudaGetSymbolAddress((void**)&wqh, g_wqh);
    cudaGetSymbolAddress((void**)&wql, g_wql);
    cudaGetSymbolAddress((void**)&woh, g_woh);
    cudaGetSymbolAddress((void**)&wol, g_wol);
    cudaGetSymbolAddress((void**)&bh,  g_bh);
    cudaGetSymbolAddress((void**)&bl,  g_bl);
    cudaGetSymbolAddress((void**)&projbuf, g_proj);

    cudaFuncSetAttribute(attn_bf3, cudaFuncAttributeMaxDynamicSharedMemorySize, AT_SMEM);
    cudaFuncSetAttribute(mm_ps<false>, cudaFuncAttributeMaxDynamicSharedMemorySize, MM_SMEM);
    cudaFuncSetAttribute(mm_ps<true>,  cudaFuncAttributeMaxDynamicSharedMemorySize, MM_SMEM);

    // 0) pre-split weights
    wsplit_kernel<<<(NPROJ*DIMN/4)/256, 256>>>(w_qkv, wqh, wql);
    wsplit_kernel<<<(DIMN*NBR/4)/256, 256>>>(w_out, woh, wol);

    // 1) LayerNorm (writes split h)
    ln_kernel<<<NROWS, 256>>>(x, gamma, beta, hh, hl);

    // 2) proj = h @ w_qkv^T   [8192 x 5120], K=1024   (128x128, 3-stage ring)
    {
        dim3 grid(NPROJ/128, NROWS/128);
        mm_ps<false><<<grid, 256, MM_SMEM>>>(hh, hl, wqh, wql, nullptr,
                                             projbuf, NROWS, NPROJ, DIMN);
    }

    // 3) GEGLU half of branch (split write)
    glu_kernel<<<(NROWS*DIMN)/4/256, 256>>>(projbuf, bh, bl);

    // 4) Attention half of branch (split write)
    {
        dim3 grid(SEQL/128, BATCH*NHEADS);
        attn_bf3<<<grid, 256, AT_SMEM>>>(projbuf, bh, bl);
    }

    // 5) out = x + branch @ w_out^T   [8192 x 1024], K=2048  (128x128, 3-stage)
    {
        dim3 grid(DIMN/128, NROWS/128);
        mm_ps<true><<<grid, 256, MM_SMEM>>>(bh, bl, woh, wol, x, out,
                                            NROWS, DIMN, NBR);
    }
}

// round 17
// speedup vs baseline: 3.9225x; 1.0226x over previous
#include <cuda_runtime.h>
#include <math.h>
#include <stdint.h>

// Problem constants
#define DIMN 1024
#define SEQL 2048
#define BATCH 4
#define NHEADS 8
#define HDIM 128
#define NROWS (BATCH*SEQL)   // 8192
#define NPROJ (5*DIMN)       // 5120
#define NBR (2*DIMN)         // 2048

// Scratch (static __device__ arrays -- allocation-free per harness rules)
// Packed bf16-pair hi/lo arrays: X[r][k/2] u32, lo16=even k, hi16=odd k.
__device__ uint32_t g_hh[(size_t)NROWS*512],  g_hl[(size_t)NROWS*512];   // LN(x)
__device__ uint32_t g_wqh[(size_t)NPROJ*512], g_wql[(size_t)NPROJ*512];  // w_qkv
__device__ uint32_t g_woh[(size_t)DIMN*1024], g_wol[(size_t)DIMN*1024]; // w_out
__device__ uint32_t g_bh[(size_t)NROWS*1024], g_bl[(size_t)NROWS*1024]; // branch
__device__ float    g_proj[(size_t)NROWS*NPROJ];                        // f32 proj

// ===========================================================================
// bf16 helpers (3xBF16 split: D += AhBh + AhBl + AlBh)
// ===========================================================================
__device__ __forceinline__ uint32_t pack_bf16(float e, float o) {
    uint32_t r;
    asm("cvt.rn.bf16x2.f32 %0, %1, %2;" : "=r"(r) : "f"(o), "f"(e));
    return r;
}
__device__ __forceinline__ float lofl(uint32_t p){ return __uint_as_float(p << 16); }
__device__ __forceinline__ float hifl(uint32_t p){ return __uint_as_float(p & 0xFFFF0000u); }

__device__ __forceinline__ void split8(float4 v0, float4 v1, uint4& h, uint4& l) {
    h.x = pack_bf16(v0.x, v0.y);
    h.y = pack_bf16(v0.z, v0.w);
    h.z = pack_bf16(v1.x, v1.y);
    h.w = pack_bf16(v1.z, v1.w);
    l.x = pack_bf16(v0.x - lofl(h.x), v0.y - hifl(h.x));
    l.y = pack_bf16(v0.z - lofl(h.y), v0.w - hifl(h.y));
    l.z = pack_bf16(v1.x - lofl(h.z), v1.y - hifl(h.z));
    l.w = pack_bf16(v1.z - lofl(h.w), v1.w - hifl(h.w));
}

__device__ __forceinline__ void mma_bf16(float* c, const uint32_t* a,
                                         const uint32_t* b) {
    asm volatile(
        "mma.sync.aligned.m16n8k16.row.col.f32.bf16.bf16.f32 "
        "{%0,%1,%2,%3}, {%4,%5,%6,%7}, {%8,%9}, {%0,%1,%2,%3};"
        : "+f"(c[0]), "+f"(c[1]), "+f"(c[2]), "+f"(c[3])
        : "r"(a[0]), "r"(a[1]), "r"(a[2]), "r"(a[3]), "r"(b[0]), "r"(b[1]));
}

__device__ __forceinline__ void ldsm4(uint32_t& r0, uint32_t& r1, uint32_t& r2,
                                      uint32_t& r3, uint32_t addr) {
    asm volatile("ldmatrix.sync.aligned.m8n8.x4.shared.b16 {%0,%1,%2,%3}, [%4];"
                 : "=r"(r0), "=r"(r1), "=r"(r2), "=r"(r3) : "r"(addr));
}

__device__ __forceinline__ uint32_t smem_u32(const void* p) {
    uint32_t a;
    asm("{ .reg .u64 t; cvta.to.shared.u64 t, %1; cvt.u32.u64 %0, t; }"
        : "=r"(a) : "l"(p));
    return a;
}
#define CP_ASYNC16(dst, src) \
    asm volatile("cp.async.ca.shared.global [%0], [%1], 16;" \
                 :: "r"(dst), "l"(src) : "memory")
#define CP_COMMIT() asm volatile("cp.async.commit_group;" ::: "memory")

// ---------------------------------------------------------------------------
// Weight split: W[R][K] f32 -> packed pair hi/lo u32 [R][K/2]
// ---------------------------------------------------------------------------
__global__ __launch_bounds__(256) void wsplit_kernel(
    const float* __restrict__ W, uint32_t* __restrict__ Wh,
    uint32_t* __restrict__ Wl)
{
    int idx = blockIdx.x*256 + threadIdx.x;
    float4 v = reinterpret_cast<const float4*>(W)[idx];
    uint32_t h0 = pack_bf16(v.x, v.y), h1 = pack_bf16(v.z, v.w);
    uint32_t l0 = pack_bf16(v.x - lofl(h0), v.y - hifl(h0));
    uint32_t l1 = pack_bf16(v.z - lofl(h1), v.w - hifl(h1));
    reinterpret_cast<uint2*>(Wh)[idx] = make_uint2(h0, h1);
    reinterpret_cast<uint2*>(Wl)[idx] = make_uint2(l0, l1);
}

// ---------------------------------------------------------------------------
// LayerNorm: one block per row of 1024; writes split packed pairs directly.
// ---------------------------------------------------------------------------
__global__ __launch_bounds__(256) void ln_kernel(
    const float* __restrict__ x, const float* __restrict__ gamma,
    const float* __restrict__ beta, uint32_t* __restrict__ hh,
    uint32_t* __restrict__ hl)
{
    int row = blockIdx.x, tid = threadIdx.x;
    const float4 v = reinterpret_cast<const float4*>(x + (size_t)row*DIMN)[tid];
    float s  = v.x + v.y + v.z + v.w;
    float sq = v.x*v.x + v.y*v.y + v.z*v.z + v.w*v.w;
    #pragma unroll
    for (int off = 16; off; off >>= 1) {
        s  += __shfl_xor_sync(0xffffffffu, s,  off);
        sq += __shfl_xor_sync(0xffffffffu, sq, off);
    }
    __shared__ float rs[8], rq[8];
    int w = tid >> 5, ln = tid & 31;
    if (ln == 0) { rs[w] = s; rq[w] = sq; }
    __syncthreads();
    s = 0.f; sq = 0.f;
    #pragma unroll
    for (int i = 0; i < 8; i++) { s += rs[i]; sq += rq[i]; }
    float mean = s * (1.f/DIMN);
    float var  = sq * (1.f/DIMN) - mean*mean;
    float rstd = rsqrtf(var + 1e-5f);
    float4 gv = reinterpret_cast<const float4*>(gamma)[tid];
    float4 bv = reinterpret_cast<const float4*>(beta)[tid];
    float4 r;
    r.x = (v.x-mean)*rstd*gv.x + bv.x;
    r.y = (v.y-mean)*rstd*gv.y + bv.y;
    r.z = (v.z-mean)*rstd*gv.z + bv.z;
    r.w = (v.w-mean)*rstd*gv.w + bv.w;
    uint32_t h0 = pack_bf16(r.x, r.y), h1 = pack_bf16(r.z, r.w);
    uint32_t l0 = pack_bf16(r.x - lofl(h0), r.y - hifl(h0));
    uint32_t l1 = pack_bf16(r.z - lofl(h1), r.w - hifl(h1));
    reinterpret_cast<uint2*>(hh + (size_t)row*512)[tid] = make_uint2(h0, h1);
    reinterpret_cast<uint2*>(hl + (size_t)row*512)[tid] = make_uint2(l0, l1);
}

// ---------------------------------------------------------------------------
// 3xBF16 GEMM (NT), pre-split operands: C = A @ B^T (+ optional Cin)
// CTA 128x128, BK=32 (16 u32 pairs), 8 warps (4x2) of 32x64 tiles.
// 3-stage cp.async ring (98 KB, 2 CTAs/SM), ONE __syncthreads per k-block,
// ldmatrix.x4 fragment loads.
// Smem layout: row-pair lines of 128B. Row r, k-granule c (0..3):
//   phys_byte = (r>>1)*128 + ((r&1)*4 + (c ^ ((r>>1)&3)))*16
// -> 8 consecutive rows at fixed c hit 8 DISTINCT bank groups (LDSM
//    conflict-free; the R15 layout had only 4 -> 2-way conflicts, smem-bound).
// ---------------------------------------------------------------------------
#define NST 3
#define STAGE_BYTES ((128 + 128)*128)          // 32768
#define MM_SMEM (NST*STAGE_BYTES)              // 98304
#define OFF_AL (128*64)                        // bytes: Al after Ah
#define OFF_BH (2*128*64)                      // bytes: Bh after Al

__device__ __forceinline__ uint32_t mm_phys(int r, int c) {
    return (uint32_t)((r >> 1)*128 + (((r & 1)*4 + (c ^ ((r >> 1) & 3))) << 4));
}

template<bool ADD>
__global__ __launch_bounds__(256, 2)
void mm_ps(const uint32_t* __restrict__ Ahg, const uint32_t* __restrict__ Alg,
           const uint32_t* __restrict__ Bhg, const uint32_t* __restrict__ Blg,
           const float* __restrict__ Cin, float* __restrict__ C,
           int M, int N, int K)
{
    extern __shared__ uint32_t smu[];
    const uint32_t sb = smem_u32(smu);
    const int tid = threadIdx.x;
    const int warp = tid >> 5, lane = tid & 31;
    const int g = lane >> 2, t4 = lane & 3;
    const int wm = (warp >> 1) * 32;
    const int wn = (warp & 1) * 64;
    const int rowBase = blockIdx.y * 128;
    const int colBase = blockIdx.x * 128;
    const int KPr = K >> 1;
    const int NKB = K >> 5;

    auto pref = [&](int st, int kb) {
        uint32_t stBase = sb + st*STAGE_BYTES;
        #pragma unroll
        for (int it = 0; it < 4; it++) {
            int idx = it*256 + tid;
            bool isB = (idx >= 512);
            int li = isB ? idx - 512 : idx;
            int r = li >> 2, c = li & 3;
            uint32_t d = stBase + (isB ? OFF_BH : 0) + mm_phys(r, c);
            size_t so = (size_t)((isB ? colBase : rowBase) + r)*KPr + kb*16 + c*4;
            CP_ASYNC16(d, (isB ? Bhg : Ahg) + so);
            CP_ASYNC16(d + 8192, (isB ? Blg : Alg) + so);
        }
    };

    // ldmatrix per-lane address precompute (row-pair swizzled layout)
    const int mid = lane >> 3, lr = lane & 7;
    const int agsel = mid >> 1;               // A k-group select
    const int bgsel = mid & 1;                // B k-group select
    int aBase[2], aSalt[2];
    #pragma unroll
    for (int mt = 0; mt < 2; mt++) {
        int row = wm + mt*16 + (mid & 1)*8 + lr;
        aBase[mt] = (row >> 1)*128 + (row & 1)*64;
        aSalt[mt] = (row >> 1) & 3;
    }
    int bBase[4], bSalt[4];
    #pragma unroll
    for (int p = 0; p < 4; p++) {
        int n = wn + p*16 + (mid >> 1)*8 + lr;
        bBase[p] = (n >> 1)*128 + (n & 1)*64;
        bSalt[p] = (n >> 1) & 3;
    }

    float acc[2][8][4];
    #pragma unroll
    for (int i = 0; i < 2; i++)
        #pragma unroll
        for (int j = 0; j < 8; j++)
            #pragma unroll
            for (int q = 0; q < 4; q++) acc[i][j][q] = 0.f;

    #pragma unroll
    for (int i = 0; i < NST-1; i++) { pref(i, i); CP_COMMIT(); }

    int stC = 0, stP = NST-1;
    for (int kb = 0; kb < NKB; kb++) {
        asm volatile("cp.async.wait_group %0;" :: "n"(NST-2) : "memory");
        __syncthreads();
        if (kb + NST-1 < NKB) pref(stP, kb + NST-1);
        CP_COMMIT();                  // dummy commit at tail keeps counts uniform

        const uint32_t stBase = sb + stC*STAGE_BYTES;
        #pragma unroll
        for (int kk = 0; kk < 2; kk++) {
            uint32_t ah[2][4], al[2][4];
            #pragma unroll
            for (int mt = 0; mt < 2; mt++) {
                uint32_t ao = stBase + aBase[mt] + (((2*kk + agsel) ^ aSalt[mt]) << 4);
                ldsm4(ah[mt][0], ah[mt][1], ah[mt][2], ah[mt][3], ao);
                ldsm4(al[mt][0], al[mt][1], al[mt][2], al[mt][3], ao + OFF_AL);
            }
            #pragma unroll
            for (int p = 0; p < 4; p++) {
                uint32_t bo = stBase + OFF_BH + bBase[p]
                            + (((2*kk + bgsel) ^ bSalt[p]) << 4);
                uint32_t bh4[4], bl4[4];
                ldsm4(bh4[0], bh4[1], bh4[2], bh4[3], bo);
                ldsm4(bl4[0], bl4[1], bl4[2], bl4[3], bo + 8192);
                #pragma unroll
                for (int mt = 0; mt < 2; mt++) {
                    mma_bf16(acc[mt][2*p],   ah[mt], bh4);
                    mma_bf16(acc[mt][2*p],   ah[mt], bl4);
                    mma_bf16(acc[mt][2*p],   al[mt], bh4);
                    mma_bf16(acc[mt][2*p+1], ah[mt], bh4 + 2);
                    mma_bf16(acc[mt][2*p+1], ah[mt], bl4 + 2);
                    mma_bf16(acc[mt][2*p+1], al[mt], bh4 + 2);
                }
            }
        }
        stC = (stC+1 == NST) ? 0 : stC+1;
        stP = (stP+1 == NST) ? 0 : stP+1;
    }

    // epilogue
    #pragma unroll
    for (int mt = 0; mt < 2; mt++) {
        int row0 = rowBase + wm + mt*16 + g;
        #pragma unroll
        for (int nt = 0; nt < 8; nt++) {
            int col = colBase + wn + nt*8 + t4*2;
            size_t o0 = (size_t)row0*N + col;
            size_t o1 = o0 + (size_t)8*N;
            float2 v0 = make_float2(acc[mt][nt][0], acc[mt][nt][1]);
            float2 v1 = make_float2(acc[mt][nt][2], acc[mt][nt][3]);
            if (ADD) {
                float2 c0 = *reinterpret_cast<const float2*>(Cin + o0);
                float2 c1 = *reinterpret_cast<const float2*>(Cin + o1);
                v0.x += c0.x; v0.y += c0.y;
                v1.x += c1.x; v1.y += c1.y;
            }
            *reinterpret_cast<float2*>(C + o0) = v0;
            *reinterpret_cast<float2*>(C + o1) = v1;
        }
    }
}

// ---------------------------------------------------------------------------
// GEGLU: writes split packed pairs into branch hi/lo (cols 0..511 pairs)
// ---------------------------------------------------------------------------
__device__ __forceinline__ float gelu_exact(float v) {
    return 0.5f * v * (1.f + erff(v * 0.70710678118654752440f));
}
__global__ __launch_bounds__(256) void glu_kernel(
    const float* __restrict__ proj, uint32_t* __restrict__ bh,
    uint32_t* __restrict__ bl)
{
    int idx = blockIdx.x * 256 + threadIdx.x;
    int r  = idx >> 8;
    int c4 = idx & 255;
    float4 lin = *reinterpret_cast<const float4*>(&proj[(size_t)r*NPROJ + 3*DIMN + c4*4]);
    float4 pre = *reinterpret_cast<const float4*>(&proj[(size_t)r*NPROJ + 4*DIMN + c4*4]);
    float4 o;
    o.x = lin.x * gelu_exact(pre.x);
    o.y = lin.y * gelu_exact(pre.y);
    o.z = lin.z * gelu_exact(pre.z);
    o.w = lin.w * gelu_exact(pre.w);
    uint32_t h0 = pack_bf16(o.x, o.y), h1 = pack_bf16(o.z, o.w);
    uint32_t l0 = pack_bf16(o.x - lofl(h0), o.y - hifl(h0));
    uint32_t l1 = pack_bf16(o.z - lofl(h1), o.w - hifl(h1));
    *reinterpret_cast<uint2*>(&bh[(size_t)r*1024 + 2*c4]) = make_uint2(h0, h1);
    *reinterpret_cast<uint2*>(&bl[(size_t)r*1024 + 2*c4]) = make_uint2(l0, l1);
}

// ---------------------------------------------------------------------------
// Flash attention (causal, p=2 power-softmax) on 3xBF16 mma.sync.
// Unchanged from R10/R15 (passing).
// ---------------------------------------------------------------------------
#define ATV 136
#define AT_SMEM ((2*128*64 + 2*64*64 + 2*32*ATV) * 4)   // 133120 B

__global__ __launch_bounds__(256, 1) void attn_bf3(
    const float* __restrict__ proj, uint32_t* __restrict__ bhg,
    uint32_t* __restrict__ blg)
{
    extern __shared__ uint32_t su[];
    uint32_t* Qh = su;               // [128][64]
    uint32_t* Ql = Qh + 128*64;
    uint32_t* Kh = Ql + 128*64;      // [64][64]
    uint32_t* Kl = Kh + 64*64;
    uint32_t* Vh = Kl + 64*64;       // [32][ATV]
    uint32_t* Vl = Vh + 32*ATV;

    const int tid = threadIdx.x;
    const int warp = tid >> 5, lane = tid & 31;
    const int g = lane >> 2, t4 = lane & 3;
    const int wm = warp * 16;
    const int qb = (SEQL/128 - 1) - blockIdx.x;     // big tiles first
    const int bh = blockIdx.y;
    const int b = bh >> 3, h = bh & 7;
    const float scale = 0.08838834764831845f;       // 1/sqrt(128)

    const size_t rowOff = (size_t)(b * SEQL) * NPROJ;
    const int colQ = h*HDIM, colK = DIMN + h*HDIM, colV = 2*DIMN + h*HDIM;

    // ---- load + split Q [128][128]
    #pragma unroll
    for (int it = 0; it < 8; it++) {
        int linear = it*256 + tid;
        int r = linear >> 4, c = linear & 15;
        const float* src = &proj[rowOff + (size_t)(qb*128 + r)*NPROJ + colQ + c*8];
        float4 v0 = *reinterpret_cast<const float4*>(src);
        float4 v1 = *reinterpret_cast<const float4*>(src + 4);
        uint4 hh, ll; split8(v0, v1, hh, ll);
        int pg = (c ^ (r & 7)) * 4;
        *reinterpret_cast<uint4*>(Qh + r*64 + pg) = hh;
        *reinterpret_cast<uint4*>(Ql + r*64 + pg) = ll;
    }

    float m[2]  = { -INFINITY, -INFINITY };
    float S2[2] = { 0.f, 0.f };
    float O[16][4];
    #pragma unroll
    for (int i = 0; i < 16; i++)
        #pragma unroll
        for (int q = 0; q < 4; q++) O[i][q] = 0.f;

    const int qg0 = qb*128 + wm + g;
    const int KT = 2*qb + 2;

    for (int kb = 0; kb < KT; kb++) {
        __syncthreads();
        // ---- load + split K tile [64][128]
        #pragma unroll
        for (int it = 0; it < 4; it++) {
            int linear = it*256 + tid;
            int r = linear >> 4, c = linear & 15;
            const float* src = &proj[rowOff + (size_t)(kb*64 + r)*NPROJ + colK + c*8];
            float4 v0 = *reinterpret_cast<const float4*>(src);
            float4 v1 = *reinterpret_cast<const float4*>(src + 4);
            uint4 hh, ll; split8(v0, v1, hh, ll);
            int pg = (c ^ (r & 7)) * 4;
            *reinterpret_cast<uint4*>(Kh + r*64 + pg) = hh;
            *reinterpret_cast<uint4*>(Kl + r*64 + pg) = ll;
        }
        // ---- load + split V tile, packed pairs along keys
        #pragma unroll
        for (int it = 0; it < 4; it++) {
            int kp = it*8 + (tid >> 5);
            int dbase = (tid & 31) * 4;
            const float* se = &proj[rowOff + (size_t)(kb*64 + 2*kp    )*NPROJ + colV + dbase];
            const float* so = &proj[rowOff + (size_t)(kb*64 + 2*kp + 1)*NPROJ + colV + dbase];
            float4 e = *reinterpret_cast<const float4*>(se);
            float4 o = *reinterpret_cast<const float4*>(so);
            uint4 hh, ll;
            hh.x = pack_bf16(e.x, o.x); ll.x = pack_bf16(e.x - lofl(hh.x), o.x - hifl(hh.x));
            hh.y = pack_bf16(e.y, o.y); ll.y = pack_bf16(e.y - lofl(hh.y), o.y - hifl(hh.y));
            hh.z = pack_bf16(e.z, o.z); ll.z = pack_bf16(e.z - lofl(hh.z), o.z - hifl(hh.z));
            hh.w = pack_bf16(e.w, o.w); ll.w = pack_bf16(e.w - lofl(hh.w), o.w - hifl(hh.w));
            *reinterpret_cast<uint4*>(Vh + kp*ATV + dbase) = hh;
            *reinterpret_cast<uint4*>(Vl + kp*ATV + dbase) = ll;
        }
        __syncthreads();

        if (kb*64 > qb*128 + wm + 15) continue;     // tile fully masked for warp

        // ---- S = Q K^T
        float s[8][4];
        #pragma unroll
        for (int nt = 0; nt < 8; nt++)
            #pragma unroll
            for (int q = 0; q < 4; q++) s[nt][q] = 0.f;
        #pragma unroll 2
        for (int kk = 0; kk < 8; kk++) {
            int c0 = ((2*kk)   ^ g)*4 + t4;
            int c1 = ((2*kk+1) ^ g)*4 + t4;
            uint32_t ah[4], al[4];
            ah[0] = Qh[(wm+g  )*64 + c0];  ah[1] = Qh[(wm+8+g)*64 + c0];
            ah[2] = Qh[(wm+g  )*64 + c1];  ah[3] = Qh[(wm+8+g)*64 + c1];
            al[0] = Ql[(wm+g  )*64 + c0];  al[1] = Ql[(wm+8+g)*64 + c0];
            al[2] = Ql[(wm+g  )*64 + c1];  al[3] = Ql[(wm+8+g)*64 + c1];
            #pragma unroll
            for (int nt = 0; nt < 8; nt++) {
                int n = nt*8 + g;
                uint32_t bh2[2] = { Kh[n*64 + c0], Kh[n*64 + c1] };
                uint32_t bl2[2] = { Kl[n*64 + c0], Kl[n*64 + c1] };
                mma_bf16(s[nt], ah, bh2);
                mma_bf16(s[nt], ah, bl2);
                mma_bf16(s[nt], al, bh2);
            }
        }

        // ---- scale + causal mask + warp-local row max
        float lmax[2] = { -INFINITY, -INFINITY };
        const bool need_mask = (kb*64 + 63 > qb*128 + wm);
        #pragma unroll
        for (int nt = 0; nt < 8; nt++)
            #pragma unroll
            for (int q = 0; q < 4; q++) {
                int ri = q >> 1;
                float v = s[nt][q] * scale;
                if (need_mask) {
                    int kg = kb*64 + nt*8 + 2*t4 + (q & 1);
                    if (kg > qg0 + 8*ri) v = -INFINITY;
                }
                s[nt][q] = v;
                lmax[ri] = fmaxf(lmax[ri], v);
            }
        #pragma unroll
        for (int off = 1; off < 4; off <<= 1) {
            lmax[0] = fmaxf(lmax[0], __shfl_xor_sync(0xffffffffu, lmax[0], off));
            lmax[1] = fmaxf(lmax[1], __shfl_xor_sync(0xffffffffu, lmax[1], off));
        }

        // ---- online p=2 softmax update
        float mn[2], corr[2], lsum[2];
        #pragma unroll
        for (int ri = 0; ri < 2; ri++) {
            mn[ri]   = fmaxf(m[ri], lmax[ri]);
            corr[ri] = __expf(m[ri] - mn[ri]);
            m[ri]    = mn[ri];
            lsum[ri] = 0.f;
        }
        #pragma unroll
        for (int nt = 0; nt < 8; nt++)
            #pragma unroll
            for (int q = 0; q < 4; q++) {
                int ri = q >> 1;
                float p = __expf(s[nt][q] - mn[ri]);
                s[nt][q] = p;
                lsum[ri] += p * p;
            }
        #pragma unroll
        for (int off = 1; off < 4; off <<= 1) {
            lsum[0] += __shfl_xor_sync(0xffffffffu, lsum[0], off);
            lsum[1] += __shfl_xor_sync(0xffffffffu, lsum[1], off);
        }
        #pragma unroll
        for (int ri = 0; ri < 2; ri++)
            S2[ri] = S2[ri]*corr[ri]*corr[ri] + lsum[ri];
        #pragma unroll
        for (int nt = 0; nt < 16; nt++)
            #pragma unroll
            for (int q = 0; q < 4; q++) O[nt][q] *= corr[q >> 1];

        // ---- O += P V
        #pragma unroll
        for (int kk = 0; kk < 4; kk++) {
            uint32_t ph[4], pl[4];
            ph[0] = pack_bf16(s[2*kk][0],   s[2*kk][1]);
            ph[1] = pack_bf16(s[2*kk][2],   s[2*kk][3]);
            ph[2] = pack_bf16(s[2*kk+1][0], s[2*kk+1][1]);
            ph[3] = pack_bf16(s[2*kk+1][2], s[2*kk+1][3]);
            pl[0] = pack_bf16(s[2*kk][0]   - lofl(ph[0]), s[2*kk][1]   - hifl(ph[0]));
            pl[1] = pack_bf16(s[2*kk][2]   - lofl(ph[1]), s[2*kk][3]   - hifl(ph[1]));
            pl[2] = pack_bf16(s[2*kk+1][0] - lofl(ph[2]), s[2*kk+1][1] - hifl(ph[2]));
            pl[3] = pack_bf16(s[2*kk+1][2] - lofl(ph[3]), s[2*kk+1][3] - hifl(ph[3]));
            int vr0 = (kk*8 + t4)*ATV;
            int vr1 = (kk*8 + 4 + t4)*ATV;
            #pragma unroll
            for (int nt = 0; nt < 16; nt++) {
                int n = nt*8 + g;
                uint32_t vbh[2] = { Vh[vr0 + n], Vh[vr1 + n] };
                uint32_t vbl[2] = { Vl[vr0 + n], Vl[vr1 + n] };
                mma_bf16(O[nt], ph, vbh);
                mma_bf16(O[nt], ph, vbl);
                mma_bf16(O[nt], pl, vbh);
            }
        }
    }

    // ---- epilogue: scale by rsqrt(S2), split-pack, store to branch hi/lo
    float inv0 = rsqrtf(S2[0]);
    float inv1 = rsqrtf(S2[1]);
    const size_t rg0 = (size_t)(b*SEQL + qb*128 + wm + g);
    const size_t rg1 = rg0 + 8;
    const int cp0 = 512 + h*64 + t4;
    #pragma unroll
    for (int nt = 0; nt < 16; nt++) {
        float a0 = O[nt][0]*inv0, a1 = O[nt][1]*inv0;
        uint32_t p0 = pack_bf16(a0, a1);
        uint32_t q0 = pack_bf16(a0 - lofl(p0), a1 - hifl(p0));
        bhg[rg0*1024 + cp0 + nt*4] = p0;
        blg[rg0*1024 + cp0 + nt*4] = q0;
        float b0 = O[nt][2]*inv1, b1 = O[nt][3]*inv1;
        uint32_t p1 = pack_bf16(b0, b1);
        uint32_t q1 = pack_bf16(b0 - lofl(p1), b1 - hifl(p1));
        bhg[rg1*1024 + cp0 + nt*4] = p1;
        blg[rg1*1024 + cp0 + nt*4] = q1;
    }
}

// ---------------------------------------------------------------------------
// Launch
// ---------------------------------------------------------------------------
extern "C" void kernel_launch(void* const* d_in, const int* in_sizes, int n_in,
                              void* d_out, int out_size)
{
    const float* x     = (const float*)d_in[0];
    const float* gamma = (const float*)d_in[1];
    const float* beta  = (const float*)d_in[2];
    const float* w_qkv = (const float*)d_in[3];
    const float* w_out = (const float*)d_in[4];
    float* out = (float*)d_out;

    uint32_t *hh, *hl, *wqh, *wql, *woh, *wol, *bh, *bl;
    float *projbuf;
    cudaGetSymbolAddress((void**)&hh,  g_hh);
    cudaGetSymbolAddress((void**)&hl,  g_hl);
    cudaGetSymbolAddress((void**)&wqh, g_wqh);
    cudaGetSymbolAddress((void**)&wql, g_wql);
    cudaGetSymbolAddress((void**)&woh, g_woh);
    cudaGetSymbolAddress((void**)&wol, g_wol);
    cudaGetSymbolAddress((void**)&bh,  g_bh);
    cudaGetSymbolAddress((void**)&bl,  g_bl);
    cudaGetSymbolAddress((void**)&projbuf, g_proj);

    cudaFuncSetAttribute(attn_bf3, cudaFuncAttributeMaxDynamicSharedMemorySize, AT_SMEM);
    cudaFuncSetAttribute(mm_ps<false>, cudaFuncAttributeMaxDynamicSharedMemorySize, MM_SMEM);
    cudaFuncSetAttribute(mm_ps<true>,  cudaFuncAttributeMaxDynamicSharedMemorySize, MM_SMEM);

    // 0) pre-split weights
    wsplit_kernel<<<(NPROJ*DIMN/4)/256, 256>>>(w_qkv, wqh, wql);
    wsplit_kernel<<<(DIMN*NBR/4)/256, 256>>>(w_out, woh, wol);

    // 1) LayerNorm (writes split h)
    ln_kernel<<<NROWS, 256>>>(x, gamma, beta, hh, hl);

    // 2) proj = h @ w_qkv^T   [8192 x 5120], K=1024   (128x128, 3-stage ring)
    {
        dim3 grid(NPROJ/128, NROWS/128);
        mm_ps<false><<<grid, 256, MM_SMEM>>>(hh, hl, wqh, wql, nullptr,
                                             projbuf, NROWS, NPROJ, DIMN);
    }

    // 3) GEGLU half of branch (split write)
    glu_kernel<<<(NROWS*DIMN)/4/256, 256>>>(projbuf, bh, bl);

    // 4) Attention half of branch (split write)
    {
        dim3 grid(SEQL/128, BATCH*NHEADS);
        attn_bf3<<<grid, 256, AT_SMEM>>>(projbuf, bh, bl);
    }

    // 5) out = x + branch @ w_out^T   [8192 x 1024], K=2048  (128x128, 3-stage)
    {
        dim3 grid(DIMN/128, NROWS/128);
        mm_ps<true><<<grid, 256, MM_SMEM>>>(bh, bl, woh, wol, x, out,
                                            NROWS, DIMN, NBR);
    }
}